// round 11
// baseline (speedup 1.0000x reference)
#include <cuda_runtime.h>
#include <math.h>
#include <stdint.h>

#define NN 50000
#define EE 1600000
#define FIN 770
#define RR 3
#define SEG (RR * NN)               // 150000
#define SCANB ((SEG + 255) / 256)   // 586

// ---------------- scratch ------------------------------------------------------
__device__ uint32_t g_xr[(size_t)RR * NN * 32];   // bf16x2 rows (64 feat = 32 u32)
__device__ float    g_bufa[(size_t)NN * 64];      // fp32 root results
__device__ float    g_bufb[(size_t)NN * 64];
__device__ uint32_t g_hb[(size_t)NN * 32];        // bf16x2 activations (h1/h2/x3)
__device__ uint32_t g_ea[(size_t)NN * 32];
__device__ uint32_t g_eb[(size_t)NN * 32];
__device__ float g_invc[SEG];
__device__ int   g_cnt[SEG];
__device__ int   g_off[SEG];
__device__ int   g_fill[SEG];
__device__ int   g_bsum[1024];
__device__ int   g_srcl[EE];
__device__ int   g_dstl[EE];
__device__ int   g_eidl[EE];
__device__ int   g_row[EE];
__device__ int   g_col[EE];
__device__ int   g_et[EE];
__device__ int   g_is64;
__device__ uint32_t g_wt1[256 * 400];   // bf16x2 pairs, [N][Kp2]
__device__ uint32_t g_wt2[256 * 32];
__device__ uint32_t g_wt3[256 * 32];
__device__ uint32_t g_wte[128 * 32];

// ---------------- helpers ------------------------------------------------------
__device__ __forceinline__ uint32_t smem_u32(const void* p) {
    uint32_t a;
    asm("{ .reg .u64 t; cvta.to.shared.u64 t, %1; cvt.u32.u64 %0, t; }" : "=r"(a) : "l"(p));
    return a;
}
__device__ __forceinline__ void cp16(uint32_t dst, const void* src, int sz) {
    asm volatile("cp.async.cg.shared.global [%0], [%1], 16, %2;"
                 :: "r"(dst), "l"(src), "r"(sz) : "memory");
}
__device__ __forceinline__ void cp8(uint32_t dst, const void* src, int sz) {
    asm volatile("cp.async.ca.shared.global [%0], [%1], 8, %2;"
                 :: "r"(dst), "l"(src), "r"(sz) : "memory");
}
__device__ __forceinline__ uint32_t f2bf2(float lo, float hi) {
    uint32_t r;
    asm("cvt.rn.bf16x2.f32 %0, %1, %2;" : "=r"(r) : "f"(hi), "f"(lo));
    return r;
}
__device__ __forceinline__ float bflo(uint32_t v) { return __uint_as_float(v << 16); }
__device__ __forceinline__ float bfhi(uint32_t v) { return __uint_as_float(v & 0xFFFF0000u); }
__device__ __forceinline__ void mma16(float* c, const uint32_t* a, uint32_t b0, uint32_t b1) {
    asm volatile(
        "mma.sync.aligned.m16n8k16.row.col.f32.bf16.bf16.f32 "
        "{%0,%1,%2,%3}, {%4,%5,%6,%7}, {%8,%9}, {%0,%1,%2,%3};"
        : "+f"(c[0]), "+f"(c[1]), "+f"(c[2]), "+f"(c[3])
        : "r"(a[0]), "r"(a[1]), "r"(a[2]), "r"(a[3]), "r"(b0), "r"(b1));
}

// ---------------- launch 1: fused detect+zero + weight pack ---------------------
__global__ void k_init(const unsigned int* __restrict__ ei,
                       const float* __restrict__ W1, const float* __restrict__ root1,
                       const float* __restrict__ W2, const float* __restrict__ root2,
                       const float* __restrict__ W3, const float* __restrict__ root3,
                       const float* __restrict__ ew1) {
    int b = blockIdx.x;
    if (b < SCANB) {
        int i = b * 256 + threadIdx.x;
        if (i < SEG) { g_cnt[i] = 0; g_fill[i] = 0; }
        if (i == 0) {
            int is64 = 1;
            for (int j = 0; j < 64; j++)
                if (ei[2 * j + 1] != 0u) { is64 = 0; break; }
            g_is64 = is64;
        }
        return;
    }
    int i = (b - SCANB) * 256 + threadIdx.x;
    if (i < 256 * 400) {                                 // wt1  [256][400]
        int n = i / 400, s = i % 400;
        int jj = s & 7, k0 = (s >> 3) * 16 + (jj >> 1) * 2 + (jj & 1) * 8;
        float lo = 0.f, hi = 0.f;
        if (n < 192) {
            if (k0 < FIN)     lo = W1[(size_t)(n >> 6) * FIN * 64 + (size_t)k0 * 64 + (n & 63)];
            if (k0 + 1 < FIN) hi = W1[(size_t)(n >> 6) * FIN * 64 + (size_t)(k0 + 1) * 64 + (n & 63)];
        } else {
            if (k0 < FIN)     lo = root1[(size_t)k0 * 64 + (n - 192)];
            if (k0 + 1 < FIN) hi = root1[(size_t)(k0 + 1) * 64 + (n - 192)];
        }
        g_wt1[i] = f2bf2(lo, hi);
        return;
    }
    int j = i - 256 * 400;
    if (j < 8192) {                                      // wt2 [256][32]
        int n = j >> 5, s = j & 31;
        int jj = s & 7, k0 = (s >> 3) * 16 + (jj >> 1) * 2 + (jj & 1) * 8;
        float lo, hi;
        if (n < 192) {
            lo = W2[(n >> 6) * 4096 + k0 * 64 + (n & 63)];
            hi = W2[(n >> 6) * 4096 + (k0 + 1) * 64 + (n & 63)];
        } else {
            lo = root2[k0 * 64 + (n - 192)];
            hi = root2[(k0 + 1) * 64 + (n - 192)];
        }
        g_wt2[j] = f2bf2(lo, hi);
        return;
    }
    j -= 8192;
    if (j < 8192) {                                      // wt3
        int n = j >> 5, s = j & 31;
        int jj = s & 7, k0 = (s >> 3) * 16 + (jj >> 1) * 2 + (jj & 1) * 8;
        float lo, hi;
        if (n < 192) {
            lo = W3[(n >> 6) * 4096 + k0 * 64 + (n & 63)];
            hi = W3[(n >> 6) * 4096 + (k0 + 1) * 64 + (n & 63)];
        } else {
            lo = root3[k0 * 64 + (n - 192)];
            hi = root3[(k0 + 1) * 64 + (n - 192)];
        }
        g_wt3[j] = f2bf2(lo, hi);
        return;
    }
    j -= 8192;
    if (j < 4096) {                                      // wte [128][32]
        int n = j >> 5, s = j & 31;
        int jj = s & 7, k0 = (s >> 3) * 16 + (jj >> 1) * 2 + (jj & 1) * 8;
        float lo, hi;
        if (n < 64) { lo = ew1[k0 * 64 + n];               hi = ew1[(k0 + 1) * 64 + n]; }
        else        { lo = ew1[(64 + k0) * 64 + (n - 64)]; hi = ew1[(64 + k0 + 1) * 64 + (n - 64)]; }
        g_wte[j] = f2bf2(lo, hi);
    }
}

// ---------------- launch 2: convert + degree count ------------------------------
__global__ void k_convert(const void* __restrict__ ei, const void* __restrict__ et) {
    int i = blockIdx.x * blockDim.x + threadIdx.x;
    if (i >= EE) return;
    int r, c, t;
    if (g_is64) {
        const long long* p = (const long long*)ei;
        r = (int)p[i];
        c = (int)p[EE + i];
        t = (int)((const long long*)et)[i];
    } else {
        const int* p = (const int*)ei;
        r = p[i];
        c = p[EE + i];
        t = ((const int*)et)[i];
    }
    g_row[i] = r; g_col[i] = c; g_et[i] = t;
    atomicAdd(&g_cnt[t * NN + c], 1);
}

// ---------------- CSR build ------------------------------------------------------
__global__ void k_bsum() {
    __shared__ int sh[256];
    int i = blockIdx.x * 256 + threadIdx.x;
    sh[threadIdx.x] = (i < SEG) ? g_cnt[i] : 0;
    __syncthreads();
    for (int o = 128; o > 0; o >>= 1) {
        if (threadIdx.x < o) sh[threadIdx.x] += sh[threadIdx.x + o];
        __syncthreads();
    }
    if (threadIdx.x == 0) g_bsum[blockIdx.x] = sh[0];
}
__global__ void k_bscan() {
    __shared__ int sh[1024];
    int tid = threadIdx.x;
    int v = (tid < SCANB) ? g_bsum[tid] : 0;
    sh[tid] = v;
    __syncthreads();
    for (int o = 1; o < 1024; o <<= 1) {
        int t = (tid >= o) ? sh[tid - o] : 0;
        __syncthreads();
        sh[tid] += t;
        __syncthreads();
    }
    if (tid < SCANB) g_bsum[tid] = sh[tid] - v;
}
__global__ void k_off() {
    __shared__ int sh[256];
    int tid = threadIdx.x;
    int i = blockIdx.x * 256 + tid;
    int v = (i < SEG) ? g_cnt[i] : 0;
    sh[tid] = v;
    __syncthreads();
    for (int o = 1; o < 256; o <<= 1) {
        int t = (tid >= o) ? sh[tid - o] : 0;
        __syncthreads();
        sh[tid] += t;
        __syncthreads();
    }
    if (i < SEG) {
        g_off[i] = sh[tid] - v + g_bsum[blockIdx.x];
        g_invc[i] = 1.0f / (float)(v > 0 ? v : 1);
    }
}
__global__ void k_scatter() {
    int e = blockIdx.x * blockDim.x + threadIdx.x;
    if (e >= EE) return;
    int c = g_col[e];
    int idx = g_et[e] * NN + c;
    int pos = g_off[idx] + atomicAdd(&g_fill[idx], 1);
    g_srcl[pos] = g_row[e];
    g_dstl[pos] = c;
    g_eidl[pos] = e;
}

// ---------------- GEMM: A (fp32 or bf16x2) @ bf16[N,Kp2]^T, N = NT*64 -----------
// 512 threads / 16 warps; MT = NT/2 row-tiles of 16 per warp; 3-stage cp.async.
// ABF=0: A fp32, smem row stride 152B, parity-aligned cp16/cp8 loads.
// ABF=1: A bf16x2, smem rows 80B, ldmatrix.
template<int NT, int ABF>
__device__ __forceinline__ void issue_chunk(const void* __restrict__ X,
                                            const uint32_t* __restrict__ Wt,
                                            int M, int K, int Kp2, int m0, int c, int buf,
                                            uint32_t sb) {
    int tid = threadIdx.x;
    uint32_t bb = sb + (ABF ? 30720u : 58368u) + (uint32_t)buf * (uint32_t)(NT * 6144);
    if (ABF) {
        uint32_t ab = sb + (uint32_t)buf * 10240u;
        int row = tid >> 2, j = tid & 3;          // 512 units: 128 rows x 4 of 16B
        int ok = (m0 + row) < M;
        const uint32_t* src = (const uint32_t*)X + (size_t)(m0 + row) * Kp2 + c * 16 + j * 4;
        cp16(ab + row * 80 + j * 16, ok ? (const void*)src : X, ok ? 16 : 0);
    } else {
        uint32_t ab = sb + (uint32_t)buf * 19456u;
        int k0 = c * 32;
#pragma unroll
        for (int i = 0; i < 4; i++) {
            int u = i * 512 + tid;                // 2048 units: 128 rows x 16 of 8B
            int row = u >> 4, j = u & 15;
            int kk = k0 + 2 * j;
            int rowok = (m0 + row) < M;
            int rem4 = (K - kk) * 4;              // may be <= 0
            const float* src = (const float*)X + (size_t)(m0 + row) * K + kk;
            uint32_t dst = ab + row * 152 + j * 8;
            if (((row + j) & 1) == 0) {
                int sz = rowok ? (rem4 > 16 ? 16 : (rem4 > 0 ? rem4 : 0)) : 0;
                cp16(dst, sz ? (const void*)src : X, sz);
            } else if (j == 0) {                  // odd-row leading straggler
                int sz = rowok ? (rem4 > 8 ? 8 : (rem4 > 0 ? rem4 : 0)) : 0;
                cp8(dst, sz ? (const void*)src : X, sz);
            }
        }
    }
#pragma unroll
    for (int i = 0; i < NT / 2; i++) {
        int u = i * 512 + tid;                    // NT*64 rows x 4 units of 16B
        int r2 = u >> 2, j2 = u & 3;
        cp16(bb + r2 * 96 + j2 * 16, Wt + (size_t)r2 * Kp2 + c * 16 + j2 * 4, 16);
    }
    asm volatile("cp.async.commit_group;" ::: "memory");
}

template<int NT, int ABF>
__global__ __launch_bounds__(512, 1) void k_mma(
    const void* __restrict__ X, const uint32_t* __restrict__ Wt,
    int M, int K, int Kp2,
    uint32_t* __restrict__ ob0, uint32_t* __restrict__ ob1,
    uint32_t* __restrict__ ob2, float* __restrict__ o3fp,
    const float* __restrict__ bias3)
{
    extern __shared__ float smf[];
    const uint32_t* smu = (const uint32_t*)smf;
    uint32_t sb = smem_u32(smf);
    const int MT = NT / 2;
    int tid = threadIdx.x, wid = tid >> 5, lane = tid & 31;
    int g = lane >> 2, tig = lane & 3;
    int wn = wid % NT, wm = wid / NT;
    int rowbase = wm * MT * 16;
    int m0 = blockIdx.x * 128;
    int NC = (K + 31) / 32;

    float acc[MT][8][4];
#pragma unroll
    for (int mt = 0; mt < MT; mt++)
#pragma unroll
        for (int nt = 0; nt < 8; nt++)
#pragma unroll
            for (int q = 0; q < 4; q++) acc[mt][nt][q] = 0.f;

    issue_chunk<NT, ABF>(X, Wt, M, K, Kp2, m0, 0, 0, sb);
    if (NC > 1) issue_chunk<NT, ABF>(X, Wt, M, K, Kp2, m0, 1, 1, sb);

    int buf = 0;
    for (int c = 0; c < NC; c++) {
        if (c + 2 < NC) {
            int b2 = buf + 2; if (b2 >= 3) b2 -= 3;
            issue_chunk<NT, ABF>(X, Wt, M, K, Kp2, m0, c + 2, b2, sb);
            asm volatile("cp.async.wait_group 2;" ::: "memory");
        } else if (c + 1 < NC) {
            asm volatile("cp.async.wait_group 1;" ::: "memory");
        } else {
            asm volatile("cp.async.wait_group 0;" ::: "memory");
        }
        __syncthreads();

        int bf = (ABF ? 7680 : 14592) + buf * (NT * 1536);   // u32 index
#pragma unroll
        for (int st = 0; st < 2; st++) {
            uint32_t A[MT][4];
#pragma unroll
            for (int mt = 0; mt < MT; mt++) {
                if (ABF) {
                    uint32_t addr = sb + (uint32_t)buf * 10240u
                        + (uint32_t)((rowbase + mt * 16 + (lane & 15)) * 80
                                     + (lane >> 4) * 16 + st * 32);
                    asm volatile(
                        "ldmatrix.sync.aligned.m8n8.x4.shared.b16 {%0,%1,%2,%3}, [%4];"
                        : "=r"(A[mt][0]), "=r"(A[mt][1]), "=r"(A[mt][2]), "=r"(A[mt][3])
                        : "r"(addr));
                } else {
                    int af = buf * 4864;                     // u32 per stage = 19456/4
                    int base = af + (rowbase + mt * 16 + g) * 38 + st * 16 + 2 * tig;
                    float2 x0 = *(const float2*)&smf[base];
                    float2 x1 = *(const float2*)&smf[base + 8 * 38];
                    float2 x2 = *(const float2*)&smf[base + 8];
                    float2 x3 = *(const float2*)&smf[base + 8 * 38 + 8];
                    A[mt][0] = f2bf2(x0.x, x0.y);
                    A[mt][1] = f2bf2(x1.x, x1.y);
                    A[mt][2] = f2bf2(x2.x, x2.y);
                    A[mt][3] = f2bf2(x3.x, x3.y);
                }
            }
#pragma unroll
            for (int nt = 0; nt < 8; nt++) {
                int nb = bf + (wn * 64 + nt * 8 + g) * 24 + st * 8 + tig * 2;
                uint2 bv = *(const uint2*)&smu[nb];
#pragma unroll
                for (int mt = 0; mt < MT; mt++)
                    mma16(acc[mt][nt], A[mt], bv.x, bv.y);
            }
        }
        __syncthreads();
        buf = (buf + 1 == 3) ? 0 : buf + 1;
    }

    bool fp = (wn == NT - 1) && (o3fp != nullptr);
    uint32_t* ob = (wn == 0) ? ob0 : ((wn == 1) ? ob1 : ob2);
#pragma unroll
    for (int mt = 0; mt < MT; mt++) {
        int mA = m0 + rowbase + mt * 16 + g;
        int mB = mA + 8;
#pragma unroll
        for (int nt = 0; nt < 8; nt++) {
            int col = nt * 8 + tig * 2;
            float c0 = acc[mt][nt][0], c1 = acc[mt][nt][1];
            float c2 = acc[mt][nt][2], c3 = acc[mt][nt][3];
            if (fp) {
                float bb0 = bias3[col], bb1 = bias3[col + 1];
                c0 += bb0; c1 += bb1; c2 += bb0; c3 += bb1;
                if (mA < M) *(float2*)(o3fp + (size_t)mA * 64 + col) = make_float2(c0, c1);
                if (mB < M) *(float2*)(o3fp + (size_t)mB * 64 + col) = make_float2(c2, c3);
            } else {
                if (mA < M) ob[(size_t)mA * 32 + (col >> 1)] = f2bf2(c0, c1);
                if (mB < M) ob[(size_t)mB * 32 + (col >> 1)] = f2bf2(c2, c3);
            }
        }
    }
}

// ---------------- CSR aggregation core: bf16 gathers (feat 2l, 2l+1) ------------
__device__ __forceinline__ void agg_core(const uint32_t* __restrict__ xr, int w, int lane,
                                         float& a0, float& a1) {
#pragma unroll
    for (int r = 0; r < RR; r++) {
        int idx = r * NN + w;
        int beg = g_off[idx], n = g_cnt[idx];
        const uint32_t* xrr = xr + (size_t)r * NN * 32;
        float s0 = 0.f, s1 = 0.f;
        for (int b = 0; b < n; b += 32) {
            int src = (b + lane < n) ? g_srcl[beg + b + lane] : 0;
            int m = min(32, n - b);
            int j = 0;
            for (; j + 8 <= m; j += 8) {
                uint32_t v[8];
#pragma unroll
                for (int q = 0; q < 8; q++)
                    v[q] = xrr[(size_t)__shfl_sync(~0u, src, j + q) * 32 + lane];
                float t0 = 0.f, t1 = 0.f;
#pragma unroll
                for (int q = 0; q < 8; q++) {
                    t0 += bflo(v[q]);
                    t1 += bfhi(v[q]);
                }
                s0 += t0; s1 += t1;
            }
            for (; j + 4 <= m; j += 4) {
                uint32_t v[4];
#pragma unroll
                for (int q = 0; q < 4; q++)
                    v[q] = xrr[(size_t)__shfl_sync(~0u, src, j + q) * 32 + lane];
#pragma unroll
                for (int q = 0; q < 4; q++) {
                    s0 += bflo(v[q]);
                    s1 += bfhi(v[q]);
                }
            }
            for (; j < m; j++) {
                uint32_t v = xrr[(size_t)__shfl_sync(~0u, src, j) * 32 + lane];
                s0 += bflo(v);
                s1 += bfhi(v);
            }
        }
        float ic = g_invc[idx];
        a0 += s0 * ic;
        a1 += s1 * ic;
    }
}

// agg + relu -> bf16x2 activation buffer
__global__ void k_agg(const uint32_t* __restrict__ xr, const float* __restrict__ io,
                      uint32_t* __restrict__ outb) {
    int w = (blockIdx.x * blockDim.x + threadIdx.x) >> 5;
    int lane = threadIdx.x & 31;
    if (w >= NN) return;
    float a0 = 0.f, a1 = 0.f;
    agg_core(xr, w, lane, a0, a1);
    float2 cur = *(const float2*)&io[(size_t)w * 64 + 2 * lane];
    float v0 = fmaxf(cur.x + a0, 0.f);
    float v1 = fmaxf(cur.y + a1, 0.f);
    outb[(size_t)w * 32 + lane] = f2bf2(v0, v1);
}

// ---------------- fused: agg(layer3) + LayerNorm + node head --------------------
__global__ void k_agg_ln_node(const uint32_t* __restrict__ xr, const float* __restrict__ io,
                              uint32_t* __restrict__ x3out,
                              const float* __restrict__ gg, const float* __restrict__ bb,
                              const float* __restrict__ nw1, const float* __restrict__ nb1,
                              const float* __restrict__ nw2, const float* __restrict__ nb2,
                              float* __restrict__ outp) {
    __shared__ float s_w1[64 * 32];
    __shared__ float s_b1[32], s_w2[64], s_b2[2], s_g[64], s_bb[64];
    int tid = threadIdx.x;
    for (int i = tid; i < 2048; i += blockDim.x) s_w1[i] = nw1[i];
    if (tid < 32) s_b1[tid] = nb1[tid];
    if (tid < 64) { s_w2[tid] = nw2[tid]; s_g[tid] = gg[tid]; s_bb[tid] = bb[tid]; }
    if (tid < 2)  s_b2[tid] = nb2[tid];
    __syncthreads();

    int w = (blockIdx.x * blockDim.x + tid) >> 5;
    int lane = tid & 31;
    if (w >= NN) return;
    float a0 = 0.f, a1 = 0.f;
    agg_core(xr, w, lane, a0, a1);
    float2 cur = *(const float2*)&io[(size_t)w * 64 + 2 * lane];
    float v0 = cur.x + a0;
    float v1 = cur.y + a1;

    float s = v0 + v1;
#pragma unroll
    for (int off = 16; off; off >>= 1) s += __shfl_xor_sync(~0u, s, off);
    float mu = s * (1.f / 64.f);
    float d0 = v0 - mu, d1 = v1 - mu;
    float q = d0 * d0 + d1 * d1;
#pragma unroll
    for (int off = 16; off; off >>= 1) q += __shfl_xor_sync(~0u, q, off);
    float rs = rsqrtf(q * (1.f / 64.f) + 1e-5f);
    float xa = d0 * rs * s_g[2 * lane]     + s_bb[2 * lane];
    float xb = d1 * rs * s_g[2 * lane + 1] + s_bb[2 * lane + 1];
    x3out[(size_t)w * 32 + lane] = f2bf2(xa, xb);

    float acc = s_b1[lane];
#pragma unroll
    for (int k = 0; k < 32; k++) {
        float x0 = __shfl_sync(~0u, xa, k);
        float x1 = __shfl_sync(~0u, xb, k);
        acc += x0 * s_w1[(2 * k) * 32 + lane] + x1 * s_w1[(2 * k + 1) * 32 + lane];
    }
    float nh = fmaxf(acc, 0.f);
    float p0 = nh * s_w2[lane * 2 + 0];
    float p1 = nh * s_w2[lane * 2 + 1];
#pragma unroll
    for (int off = 16; off; off >>= 1) {
        p0 += __shfl_xor_sync(~0u, p0, off);
        p1 += __shfl_xor_sync(~0u, p1, off);
    }
    if (lane == 0) {
        float l0 = p0 + s_b2[0], l1 = p1 + s_b2[1];
        float mx = fmaxf(l0, l1);
        float lse = __logf(__expf(l0 - mx) + __expf(l1 - mx)) + mx;
        outp[(size_t)3 * EE + (size_t)w * 2 + 0] = l0 - lse;
        outp[(size_t)3 * EE + (size_t)w * 2 + 1] = l1 - lse;
    }
}

// ---------------- edge classifier, CSR order, bf16 gathers ----------------------
__global__ void k_edge(const uint2* __restrict__ ea2, const uint2* __restrict__ eb2v,
                       const float* __restrict__ eb1, const float* __restrict__ ew2,
                       const float* __restrict__ eb2, float* __restrict__ outp) {
    __shared__ float s_b1[64], s_w2[192], s_b2[3];
    int tid = threadIdx.x;
    if (tid < 64)  s_b1[tid] = eb1[tid];
    if (tid < 192) s_w2[tid] = ew2[tid];
    if (tid < 3)   s_b2[tid] = eb2[tid];
    __syncthreads();

    int gid = blockIdx.x * blockDim.x + tid;
    int p = gid >> 4, sub = tid & 15;
    if (p >= EE) return;
    int r  = g_srcl[p];
    int c  = g_dstl[p];
    int id = g_eidl[p];
    uint2 va = ea2[(size_t)r * 16 + sub];
    uint2 vb = eb2v[(size_t)c * 16 + sub];
    float h[4];
    h[0] = fmaxf(bflo(va.x) + bflo(vb.x) + s_b1[sub * 4 + 0], 0.f);
    h[1] = fmaxf(bfhi(va.x) + bfhi(vb.x) + s_b1[sub * 4 + 1], 0.f);
    h[2] = fmaxf(bflo(va.y) + bflo(vb.y) + s_b1[sub * 4 + 2], 0.f);
    h[3] = fmaxf(bfhi(va.y) + bfhi(vb.y) + s_b1[sub * 4 + 3], 0.f);
    float p0 = 0.f, p1 = 0.f, p2 = 0.f;
#pragma unroll
    for (int i = 0; i < 4; i++) {
        int f = sub * 4 + i;
        p0 += h[i] * s_w2[f * 3 + 0];
        p1 += h[i] * s_w2[f * 3 + 1];
        p2 += h[i] * s_w2[f * 3 + 2];
    }
#pragma unroll
    for (int off = 8; off; off >>= 1) {
        p0 += __shfl_xor_sync(~0u, p0, off);
        p1 += __shfl_xor_sync(~0u, p1, off);
        p2 += __shfl_xor_sync(~0u, p2, off);
    }
    if (sub == 0) {
        float l0 = p0 + s_b2[0], l1 = p1 + s_b2[1], l2 = p2 + s_b2[2];
        float mx = fmaxf(l0, fmaxf(l1, l2));
        float lse = __logf(__expf(l0 - mx) + __expf(l1 - mx) + __expf(l2 - mx)) + mx;
        outp[(size_t)id * 3 + 0] = l0 - lse;
        outp[(size_t)id * 3 + 1] = l1 - lse;
        outp[(size_t)id * 3 + 2] = l2 - lse;
    }
}

// ---------------- host orchestration -------------------------------------------
extern "C" void kernel_launch(void* const* d_in, const int* in_sizes, int n_in,
                              void* d_out, int out_size) {
    const float* x     = (const float*)d_in[0];
    const void*  eidx  = d_in[1];
    const void*  etyp  = d_in[2];
    const float* W1    = (const float*)d_in[3];
    const float* root1 = (const float*)d_in[4];
    const float* b1    = (const float*)d_in[5];
    const float* W2    = (const float*)d_in[6];
    const float* root2 = (const float*)d_in[7];
    const float* b2    = (const float*)d_in[8];
    const float* W3    = (const float*)d_in[9];
    const float* root3 = (const float*)d_in[10];
    const float* b3    = (const float*)d_in[11];
    const float* ln_g  = (const float*)d_in[12];
    const float* ln_b  = (const float*)d_in[13];
    const float* ew1   = (const float*)d_in[14];
    const float* eb1   = (const float*)d_in[15];
    const float* ew2   = (const float*)d_in[16];
    const float* eb2   = (const float*)d_in[17];
    const float* nw1   = (const float*)d_in[18];
    const float* nb1   = (const float*)d_in[19];
    const float* nw2   = (const float*)d_in[20];
    const float* nb2   = (const float*)d_in[21];
    float* out = (float*)d_out;

    float *p_bufa, *p_bufb;
    uint32_t *p_xr, *p_hb, *p_ea, *p_eb, *p_wt1, *p_wt2, *p_wt3, *p_wte;
    cudaGetSymbolAddress((void**)&p_xr,   g_xr);
    cudaGetSymbolAddress((void**)&p_bufa, g_bufa);
    cudaGetSymbolAddress((void**)&p_bufb, g_bufb);
    cudaGetSymbolAddress((void**)&p_hb,   g_hb);
    cudaGetSymbolAddress((void**)&p_ea,   g_ea);
    cudaGetSymbolAddress((void**)&p_eb,   g_eb);
    cudaGetSymbolAddress((void**)&p_wt1,  g_wt1);
    cudaGetSymbolAddress((void**)&p_wt2,  g_wt2);
    cudaGetSymbolAddress((void**)&p_wt3,  g_wt3);
    cudaGetSymbolAddress((void**)&p_wte,  g_wte);

    const int SMEM_F4 = 58368 + 3 * 4 * 6144;   // 132096 B (fp32-A, NT=4)
    const int SMEM_B4 = 30720 + 3 * 4 * 6144;   // 104448 B (bf16-A, NT=4)
    const int SMEM_B2 = 30720 + 3 * 2 * 6144;   //  67584 B (bf16-A, NT=2)
    cudaFuncSetAttribute((const void*)k_mma<4, 0>, cudaFuncAttributeMaxDynamicSharedMemorySize, SMEM_F4);
    cudaFuncSetAttribute((const void*)k_mma<4, 1>, cudaFuncAttributeMaxDynamicSharedMemorySize, SMEM_B4);
    cudaFuncSetAttribute((const void*)k_mma<2, 1>, cudaFuncAttributeMaxDynamicSharedMemorySize, SMEM_B2);

    int tiles = (NN + 127) / 128;            // 391
    int warpNBlocks = (NN * 32 + 255) / 256;
    int packN = 256 * 400 + 8192 + 8192 + 4096;
    int initB = SCANB + (packN + 255) / 256;
    size_t NH32 = (size_t)NN * 32;

    // 1-4: init(zero+detect+pack), convert+count, bsum, layer-1 GEMM (profiled)
    k_init<<<initB, 256>>>((const unsigned int*)eidx, W1, root1, W2, root2, W3, root3, ew1);
    k_convert<<<(EE + 255) / 256, 256>>>(eidx, etyp);
    k_bsum<<<SCANB, 256>>>();
    k_mma<4, 0><<<tiles, 512, SMEM_F4>>>(x, p_wt1, NN, FIN, 400,
                                         p_xr, p_xr + NH32, p_xr + 2 * NH32, p_bufa, b1);

    // 5-7: rest of CSR build
    k_bscan<<<1, 1024>>>();
    k_off<<<SCANB, 256>>>();
    k_scatter<<<(EE + 255) / 256, 256>>>();

    // 8: layer-1 aggregate + relu -> bf16 h1
    k_agg<<<warpNBlocks, 256>>>(p_xr, p_bufa, p_hb);

    // 9-10: layer 2 (A = bf16 h1)
    k_mma<4, 1><<<tiles, 512, SMEM_B4>>>(p_hb, p_wt2, NN, 64, 32,
                                         p_xr, p_xr + NH32, p_xr + 2 * NH32, p_bufb, b2);
    k_agg<<<warpNBlocks, 256>>>(p_xr, p_bufb, p_hb);

    // 11-12: layer 3 + fused agg/LN/node-head (x3 bf16 -> g_hb)
    k_mma<4, 1><<<tiles, 512, SMEM_B4>>>(p_hb, p_wt3, NN, 64, 32,
                                         p_xr, p_xr + NH32, p_xr + 2 * NH32, p_bufa, b3);
    k_agg_ln_node<<<warpNBlocks, 256>>>(p_xr, p_bufa, p_hb, ln_g, ln_b,
                                        nw1, nb1, nw2, nb2, out);

    // 13-14: edge head (A = x3 bf16)
    k_mma<2, 1><<<tiles, 512, SMEM_B2>>>(p_hb, p_wte, NN, 64, 32,
                                         p_ea, p_eb, nullptr, nullptr, nullptr);
    k_edge<<<(EE * 16 + 255) / 256, 256>>>((const uint2*)p_ea, (const uint2*)p_eb,
                                           eb1, ew2, eb2, out);
}

// round 12
// speedup vs baseline: 1.0249x; 1.0249x over previous
#include <cuda_runtime.h>
#include <math.h>
#include <stdint.h>

#define NN 50000
#define EE 1600000
#define FIN 770
#define RR 3
#define SEG (RR * NN)               // 150000
#define SCANB ((SEG + 255) / 256)   // 586

// ---------------- scratch ------------------------------------------------------
__device__ uint32_t g_xr[(size_t)RR * NN * 32];   // bf16x2 rows (64 feat = 32 u32)
__device__ float    g_bufa[(size_t)NN * 64];      // fp32 root results
__device__ float    g_bufb[(size_t)NN * 64];
__device__ uint32_t g_hb[(size_t)NN * 32];        // bf16x2 activations (h1/h2/x3)
__device__ uint32_t g_ea[(size_t)NN * 32];
__device__ uint32_t g_eb[(size_t)NN * 32];
__device__ float g_invc[SEG];
__device__ int   g_cnt[SEG];
__device__ int   g_off[SEG];
__device__ int   g_fill[SEG];
__device__ int   g_bsum[1024];
__device__ int   g_srcl[EE];
__device__ int   g_dstl[EE];
__device__ int   g_eidl[EE];
__device__ int   g_row[EE];
__device__ int   g_col[EE];
__device__ int   g_et[EE];
__device__ int   g_is64;
__device__ uint32_t g_wt1[256 * 400];   // bf16x2 pairs, [N][Kp2]
__device__ uint32_t g_wt2[256 * 32];
__device__ uint32_t g_wt3[256 * 32];
__device__ uint32_t g_wte[128 * 32];

// ---------------- helpers ------------------------------------------------------
__device__ __forceinline__ uint32_t smem_u32(const void* p) {
    uint32_t a;
    asm("{ .reg .u64 t; cvta.to.shared.u64 t, %1; cvt.u32.u64 %0, t; }" : "=r"(a) : "l"(p));
    return a;
}
__device__ __forceinline__ void cp16(uint32_t dst, const void* src, int sz) {
    asm volatile("cp.async.cg.shared.global [%0], [%1], 16, %2;"
                 :: "r"(dst), "l"(src), "r"(sz) : "memory");
}
__device__ __forceinline__ void cp8(uint32_t dst, const void* src, int sz) {
    asm volatile("cp.async.ca.shared.global [%0], [%1], 8, %2;"
                 :: "r"(dst), "l"(src), "r"(sz) : "memory");
}
__device__ __forceinline__ uint32_t f2bf2(float lo, float hi) {
    uint32_t r;
    asm("cvt.rn.bf16x2.f32 %0, %1, %2;" : "=r"(r) : "f"(hi), "f"(lo));
    return r;
}
__device__ __forceinline__ float bflo(uint32_t v) { return __uint_as_float(v << 16); }
__device__ __forceinline__ float bfhi(uint32_t v) { return __uint_as_float(v & 0xFFFF0000u); }
__device__ __forceinline__ void mma16(float* c, const uint32_t* a, uint32_t b0, uint32_t b1) {
    asm volatile(
        "mma.sync.aligned.m16n8k16.row.col.f32.bf16.bf16.f32 "
        "{%0,%1,%2,%3}, {%4,%5,%6,%7}, {%8,%9}, {%0,%1,%2,%3};"
        : "+f"(c[0]), "+f"(c[1]), "+f"(c[2]), "+f"(c[3])
        : "r"(a[0]), "r"(a[1]), "r"(a[2]), "r"(a[3]), "r"(b0), "r"(b1));
}

// ---------------- launch 1: fused detect+zero + weight pack ---------------------
__global__ void k_init(const unsigned int* __restrict__ ei,
                       const float* __restrict__ W1, const float* __restrict__ root1,
                       const float* __restrict__ W2, const float* __restrict__ root2,
                       const float* __restrict__ W3, const float* __restrict__ root3,
                       const float* __restrict__ ew1) {
    int b = blockIdx.x;
    if (b < SCANB) {
        int i = b * 256 + threadIdx.x;
        if (i < SEG) { g_cnt[i] = 0; g_fill[i] = 0; }
        if (i == 0) {
            int is64 = 1;
            for (int j = 0; j < 64; j++)
                if (ei[2 * j + 1] != 0u) { is64 = 0; break; }
            g_is64 = is64;
        }
        return;
    }
    int i = (b - SCANB) * 256 + threadIdx.x;
    if (i < 256 * 400) {                                 // wt1  [256][400]
        int n = i / 400, s = i % 400;
        int jj = s & 7, k0 = (s >> 3) * 16 + (jj >> 1) * 2 + (jj & 1) * 8;
        float lo = 0.f, hi = 0.f;
        if (n < 192) {
            if (k0 < FIN)     lo = W1[(size_t)(n >> 6) * FIN * 64 + (size_t)k0 * 64 + (n & 63)];
            if (k0 + 1 < FIN) hi = W1[(size_t)(n >> 6) * FIN * 64 + (size_t)(k0 + 1) * 64 + (n & 63)];
        } else {
            if (k0 < FIN)     lo = root1[(size_t)k0 * 64 + (n - 192)];
            if (k0 + 1 < FIN) hi = root1[(size_t)(k0 + 1) * 64 + (n - 192)];
        }
        g_wt1[i] = f2bf2(lo, hi);
        return;
    }
    int j = i - 256 * 400;
    if (j < 8192) {                                      // wt2 [256][32]
        int n = j >> 5, s = j & 31;
        int jj = s & 7, k0 = (s >> 3) * 16 + (jj >> 1) * 2 + (jj & 1) * 8;
        float lo, hi;
        if (n < 192) {
            lo = W2[(n >> 6) * 4096 + k0 * 64 + (n & 63)];
            hi = W2[(n >> 6) * 4096 + (k0 + 1) * 64 + (n & 63)];
        } else {
            lo = root2[k0 * 64 + (n - 192)];
            hi = root2[(k0 + 1) * 64 + (n - 192)];
        }
        g_wt2[j] = f2bf2(lo, hi);
        return;
    }
    j -= 8192;
    if (j < 8192) {                                      // wt3
        int n = j >> 5, s = j & 31;
        int jj = s & 7, k0 = (s >> 3) * 16 + (jj >> 1) * 2 + (jj & 1) * 8;
        float lo, hi;
        if (n < 192) {
            lo = W3[(n >> 6) * 4096 + k0 * 64 + (n & 63)];
            hi = W3[(n >> 6) * 4096 + (k0 + 1) * 64 + (n & 63)];
        } else {
            lo = root3[k0 * 64 + (n - 192)];
            hi = root3[(k0 + 1) * 64 + (n - 192)];
        }
        g_wt3[j] = f2bf2(lo, hi);
        return;
    }
    j -= 8192;
    if (j < 4096) {                                      // wte [128][32]
        int n = j >> 5, s = j & 31;
        int jj = s & 7, k0 = (s >> 3) * 16 + (jj >> 1) * 2 + (jj & 1) * 8;
        float lo, hi;
        if (n < 64) { lo = ew1[k0 * 64 + n];               hi = ew1[(k0 + 1) * 64 + n]; }
        else        { lo = ew1[(64 + k0) * 64 + (n - 64)]; hi = ew1[(64 + k0 + 1) * 64 + (n - 64)]; }
        g_wte[j] = f2bf2(lo, hi);
    }
}

// ---------------- launch 2: convert + degree count ------------------------------
__global__ void k_convert(const void* __restrict__ ei, const void* __restrict__ et) {
    int i = blockIdx.x * blockDim.x + threadIdx.x;
    if (i >= EE) return;
    int r, c, t;
    if (g_is64) {
        const long long* p = (const long long*)ei;
        r = (int)p[i];
        c = (int)p[EE + i];
        t = (int)((const long long*)et)[i];
    } else {
        const int* p = (const int*)ei;
        r = p[i];
        c = p[EE + i];
        t = ((const int*)et)[i];
    }
    g_row[i] = r; g_col[i] = c; g_et[i] = t;
    atomicAdd(&g_cnt[t * NN + c], 1);
}

// ---------------- CSR build ------------------------------------------------------
__global__ void k_bsum() {
    __shared__ int sh[256];
    int i = blockIdx.x * 256 + threadIdx.x;
    sh[threadIdx.x] = (i < SEG) ? g_cnt[i] : 0;
    __syncthreads();
    for (int o = 128; o > 0; o >>= 1) {
        if (threadIdx.x < o) sh[threadIdx.x] += sh[threadIdx.x + o];
        __syncthreads();
    }
    if (threadIdx.x == 0) g_bsum[blockIdx.x] = sh[0];
}
__global__ void k_bscan() {
    __shared__ int sh[1024];
    int tid = threadIdx.x;
    int v = (tid < SCANB) ? g_bsum[tid] : 0;
    sh[tid] = v;
    __syncthreads();
    for (int o = 1; o < 1024; o <<= 1) {
        int t = (tid >= o) ? sh[tid - o] : 0;
        __syncthreads();
        sh[tid] += t;
        __syncthreads();
    }
    if (tid < SCANB) g_bsum[tid] = sh[tid] - v;
}
__global__ void k_off() {
    __shared__ int sh[256];
    int tid = threadIdx.x;
    int i = blockIdx.x * 256 + tid;
    int v = (i < SEG) ? g_cnt[i] : 0;
    sh[tid] = v;
    __syncthreads();
    for (int o = 1; o < 256; o <<= 1) {
        int t = (tid >= o) ? sh[tid - o] : 0;
        __syncthreads();
        sh[tid] += t;
        __syncthreads();
    }
    if (i < SEG) {
        g_off[i] = sh[tid] - v + g_bsum[blockIdx.x];
        g_invc[i] = 1.0f / (float)(v > 0 ? v : 1);
    }
}
__global__ void k_scatter() {
    int e = blockIdx.x * blockDim.x + threadIdx.x;
    if (e >= EE) return;
    int c = g_col[e];
    int idx = g_et[e] * NN + c;
    int pos = g_off[idx] + atomicAdd(&g_fill[idx], 1);
    g_srcl[pos] = g_row[e];
    g_dstl[pos] = c;
    g_eidl[pos] = e;
}

// ---------------- GEMM: A (fp32 or bf16x2) @ bf16[N,Kp2]^T, N = NT*64 -----------
// 512 threads / 16 warps; MT = NT/2 row-tiles of 16 per warp; 3-stage cp.async.
// ABF=0: A fp32, smem row stride 152B; divergence-free parity cp16 mapping:
//   thread -> (row, slot 0..7), j = 2*slot + (row&1); odd-row unit 0 via tid<64 cp8.
// ABF=1: A bf16x2, smem rows 80B, ldmatrix.
template<int NT, int ABF>
__device__ __forceinline__ void issue_chunk(const void* __restrict__ X,
                                            const uint32_t* __restrict__ Wt,
                                            int M, int K, int Kp2, int m0, int c, int buf,
                                            uint32_t sb) {
    int tid = threadIdx.x;
    uint32_t bb = sb + (ABF ? 30720u : 58368u) + (uint32_t)buf * (uint32_t)(NT * 6144);
    if (ABF) {
        uint32_t ab = sb + (uint32_t)buf * 10240u;
        int row = tid >> 2, j = tid & 3;          // 512 units: 128 rows x 4 of 16B
        int ok = (m0 + row) < M;
        const uint32_t* src = (const uint32_t*)X + (size_t)(m0 + row) * Kp2 + c * 16 + j * 4;
        cp16(ab + row * 80 + j * 16, ok ? (const void*)src : X, ok ? 16 : 0);
    } else {
        uint32_t ab = sb + (uint32_t)buf * 19456u;
        int k0 = c * 32;
#pragma unroll
        for (int i = 0; i < 2; i++) {
            int u = i * 512 + tid;                // 1024 units: 128 rows x 8 slots
            int row = u >> 3, slot = u & 7;
            int j = 2 * slot + (row & 1);         // arithmetic parity, no branch
            int kk = k0 + 2 * j;
            int rem4 = (K - kk) * 4;
            int sz = ((m0 + row) < M) ? (rem4 > 16 ? 16 : (rem4 > 0 ? rem4 : 0)) : 0;
            const float* src = (const float*)X + (size_t)(m0 + row) * K + kk;
            cp16(ab + row * 152 + j * 8, sz ? (const void*)src : X, sz);
        }
        if (tid < 64) {                           // odd-row unit 0 (uniform warps)
            int row = 2 * tid + 1;
            int rem4 = (K - k0) * 4;
            int sz = ((m0 + row) < M) ? (rem4 > 8 ? 8 : (rem4 > 0 ? rem4 : 0)) : 0;
            const float* src = (const float*)X + (size_t)(m0 + row) * K + k0;
            cp8(ab + row * 152, sz ? (const void*)src : X, sz);
        }
    }
#pragma unroll
    for (int i = 0; i < NT / 2; i++) {
        int u = i * 512 + tid;                    // NT*64 rows x 4 units of 16B
        int r2 = u >> 2, j2 = u & 3;
        cp16(bb + r2 * 96 + j2 * 16, Wt + (size_t)r2 * Kp2 + c * 16 + j2 * 4, 16);
    }
    asm volatile("cp.async.commit_group;" ::: "memory");
}

template<int NT, int ABF>
__global__ __launch_bounds__(512, 1) void k_mma(
    const void* __restrict__ X, const uint32_t* __restrict__ Wt,
    int M, int K, int Kp2,
    uint32_t* __restrict__ ob0, uint32_t* __restrict__ ob1,
    uint32_t* __restrict__ ob2, float* __restrict__ o3fp,
    const float* __restrict__ bias3)
{
    extern __shared__ float smf[];
    const uint32_t* smu = (const uint32_t*)smf;
    uint32_t sb = smem_u32(smf);
    const int MT = NT / 2;
    int tid = threadIdx.x, wid = tid >> 5, lane = tid & 31;
    int g = lane >> 2, tig = lane & 3;
    int wn = wid % NT, wm = wid / NT;
    int rowbase = wm * MT * 16;
    int m0 = blockIdx.x * 128;
    int NC = (K + 31) / 32;

    float acc[MT][8][4];
#pragma unroll
    for (int mt = 0; mt < MT; mt++)
#pragma unroll
        for (int nt = 0; nt < 8; nt++)
#pragma unroll
            for (int q = 0; q < 4; q++) acc[mt][nt][q] = 0.f;

    issue_chunk<NT, ABF>(X, Wt, M, K, Kp2, m0, 0, 0, sb);
    if (NC > 1) issue_chunk<NT, ABF>(X, Wt, M, K, Kp2, m0, 1, 1, sb);

    int buf = 0;
    for (int c = 0; c < NC; c++) {
        if (c + 2 < NC) {
            int b2 = buf + 2; if (b2 >= 3) b2 -= 3;
            issue_chunk<NT, ABF>(X, Wt, M, K, Kp2, m0, c + 2, b2, sb);
            asm volatile("cp.async.wait_group 2;" ::: "memory");
        } else if (c + 1 < NC) {
            asm volatile("cp.async.wait_group 1;" ::: "memory");
        } else {
            asm volatile("cp.async.wait_group 0;" ::: "memory");
        }
        __syncthreads();

        int bf = (ABF ? 7680 : 14592) + buf * (NT * 1536);   // u32 index
#pragma unroll
        for (int st = 0; st < 2; st++) {
            uint32_t A[MT][4];
#pragma unroll
            for (int mt = 0; mt < MT; mt++) {
                if (ABF) {
                    uint32_t addr = sb + (uint32_t)buf * 10240u
                        + (uint32_t)((rowbase + mt * 16 + (lane & 15)) * 80
                                     + (lane >> 4) * 16 + st * 32);
                    asm volatile(
                        "ldmatrix.sync.aligned.m8n8.x4.shared.b16 {%0,%1,%2,%3}, [%4];"
                        : "=r"(A[mt][0]), "=r"(A[mt][1]), "=r"(A[mt][2]), "=r"(A[mt][3])
                        : "r"(addr));
                } else {
                    int af = buf * 4864;                     // u32 per stage = 19456/4
                    int base = af + (rowbase + mt * 16 + g) * 38 + st * 16 + 2 * tig;
                    float2 x0 = *(const float2*)&smf[base];
                    float2 x1 = *(const float2*)&smf[base + 8 * 38];
                    float2 x2 = *(const float2*)&smf[base + 8];
                    float2 x3 = *(const float2*)&smf[base + 8 * 38 + 8];
                    A[mt][0] = f2bf2(x0.x, x0.y);
                    A[mt][1] = f2bf2(x1.x, x1.y);
                    A[mt][2] = f2bf2(x2.x, x2.y);
                    A[mt][3] = f2bf2(x3.x, x3.y);
                }
            }
#pragma unroll
            for (int nt = 0; nt < 8; nt++) {
                int nb = bf + (wn * 64 + nt * 8 + g) * 24 + st * 8 + tig * 2;
                uint2 bv = *(const uint2*)&smu[nb];
#pragma unroll
                for (int mt = 0; mt < MT; mt++)
                    mma16(acc[mt][nt], A[mt], bv.x, bv.y);
            }
        }
        __syncthreads();
        buf = (buf + 1 == 3) ? 0 : buf + 1;
    }

    bool fp = (wn == NT - 1) && (o3fp != nullptr);
    uint32_t* ob = (wn == 0) ? ob0 : ((wn == 1) ? ob1 : ob2);
#pragma unroll
    for (int mt = 0; mt < MT; mt++) {
        int mA = m0 + rowbase + mt * 16 + g;
        int mB = mA + 8;
#pragma unroll
        for (int nt = 0; nt < 8; nt++) {
            int col = nt * 8 + tig * 2;
            float c0 = acc[mt][nt][0], c1 = acc[mt][nt][1];
            float c2 = acc[mt][nt][2], c3 = acc[mt][nt][3];
            if (fp) {
                float bb0 = bias3[col], bb1 = bias3[col + 1];
                c0 += bb0; c1 += bb1; c2 += bb0; c3 += bb1;
                if (mA < M) *(float2*)(o3fp + (size_t)mA * 64 + col) = make_float2(c0, c1);
                if (mB < M) *(float2*)(o3fp + (size_t)mB * 64 + col) = make_float2(c2, c3);
            } else {
                if (mA < M) ob[(size_t)mA * 32 + (col >> 1)] = f2bf2(c0, c1);
                if (mB < M) ob[(size_t)mB * 32 + (col >> 1)] = f2bf2(c2, c3);
            }
        }
    }
}

// ---------------- CSR aggregation core: bf16 gathers (feat 2l, 2l+1) ------------
__device__ __forceinline__ void agg_core(const uint32_t* __restrict__ xr, int w, int lane,
                                         float& a0, float& a1) {
#pragma unroll
    for (int r = 0; r < RR; r++) {
        int idx = r * NN + w;
        int beg = g_off[idx], n = g_cnt[idx];
        const uint32_t* xrr = xr + (size_t)r * NN * 32;
        float s0 = 0.f, s1 = 0.f;
        for (int b = 0; b < n; b += 32) {
            int src = (b + lane < n) ? g_srcl[beg + b + lane] : 0;
            int m = min(32, n - b);
            int j = 0;
            for (; j + 8 <= m; j += 8) {
                uint32_t v[8];
#pragma unroll
                for (int q = 0; q < 8; q++)
                    v[q] = xrr[(size_t)__shfl_sync(~0u, src, j + q) * 32 + lane];
                float t0 = 0.f, t1 = 0.f;
#pragma unroll
                for (int q = 0; q < 8; q++) {
                    t0 += bflo(v[q]);
                    t1 += bfhi(v[q]);
                }
                s0 += t0; s1 += t1;
            }
            for (; j + 4 <= m; j += 4) {
                uint32_t v[4];
#pragma unroll
                for (int q = 0; q < 4; q++)
                    v[q] = xrr[(size_t)__shfl_sync(~0u, src, j + q) * 32 + lane];
#pragma unroll
                for (int q = 0; q < 4; q++) {
                    s0 += bflo(v[q]);
                    s1 += bfhi(v[q]);
                }
            }
            for (; j < m; j++) {
                uint32_t v = xrr[(size_t)__shfl_sync(~0u, src, j) * 32 + lane];
                s0 += bflo(v);
                s1 += bfhi(v);
            }
        }
        float ic = g_invc[idx];
        a0 += s0 * ic;
        a1 += s1 * ic;
    }
}

// agg + relu -> bf16x2 activation buffer
__global__ void k_agg(const uint32_t* __restrict__ xr, const float* __restrict__ io,
                      uint32_t* __restrict__ outb) {
    int w = (blockIdx.x * blockDim.x + threadIdx.x) >> 5;
    int lane = threadIdx.x & 31;
    if (w >= NN) return;
    float a0 = 0.f, a1 = 0.f;
    agg_core(xr, w, lane, a0, a1);
    float2 cur = *(const float2*)&io[(size_t)w * 64 + 2 * lane];
    float v0 = fmaxf(cur.x + a0, 0.f);
    float v1 = fmaxf(cur.y + a1, 0.f);
    outb[(size_t)w * 32 + lane] = f2bf2(v0, v1);
}

// ---------------- fused: agg(layer3) + LayerNorm + node head --------------------
__global__ void k_agg_ln_node(const uint32_t* __restrict__ xr, const float* __restrict__ io,
                              uint32_t* __restrict__ x3out,
                              const float* __restrict__ gg, const float* __restrict__ bb,
                              const float* __restrict__ nw1, const float* __restrict__ nb1,
                              const float* __restrict__ nw2, const float* __restrict__ nb2,
                              float* __restrict__ outp) {
    __shared__ float s_w1[64 * 32];
    __shared__ float s_b1[32], s_w2[64], s_b2[2], s_g[64], s_bb[64];
    int tid = threadIdx.x;
    for (int i = tid; i < 2048; i += blockDim.x) s_w1[i] = nw1[i];
    if (tid < 32) s_b1[tid] = nb1[tid];
    if (tid < 64) { s_w2[tid] = nw2[tid]; s_g[tid] = gg[tid]; s_bb[tid] = bb[tid]; }
    if (tid < 2)  s_b2[tid] = nb2[tid];
    __syncthreads();

    int w = (blockIdx.x * blockDim.x + tid) >> 5;
    int lane = tid & 31;
    if (w >= NN) return;
    float a0 = 0.f, a1 = 0.f;
    agg_core(xr, w, lane, a0, a1);
    float2 cur = *(const float2*)&io[(size_t)w * 64 + 2 * lane];
    float v0 = cur.x + a0;
    float v1 = cur.y + a1;

    float s = v0 + v1;
#pragma unroll
    for (int off = 16; off; off >>= 1) s += __shfl_xor_sync(~0u, s, off);
    float mu = s * (1.f / 64.f);
    float d0 = v0 - mu, d1 = v1 - mu;
    float q = d0 * d0 + d1 * d1;
#pragma unroll
    for (int off = 16; off; off >>= 1) q += __shfl_xor_sync(~0u, q, off);
    float rs = rsqrtf(q * (1.f / 64.f) + 1e-5f);
    float xa = d0 * rs * s_g[2 * lane]     + s_bb[2 * lane];
    float xb = d1 * rs * s_g[2 * lane + 1] + s_bb[2 * lane + 1];
    x3out[(size_t)w * 32 + lane] = f2bf2(xa, xb);

    float acc = s_b1[lane];
#pragma unroll
    for (int k = 0; k < 32; k++) {
        float x0 = __shfl_sync(~0u, xa, k);
        float x1 = __shfl_sync(~0u, xb, k);
        acc += x0 * s_w1[(2 * k) * 32 + lane] + x1 * s_w1[(2 * k + 1) * 32 + lane];
    }
    float nh = fmaxf(acc, 0.f);
    float p0 = nh * s_w2[lane * 2 + 0];
    float p1 = nh * s_w2[lane * 2 + 1];
#pragma unroll
    for (int off = 16; off; off >>= 1) {
        p0 += __shfl_xor_sync(~0u, p0, off);
        p1 += __shfl_xor_sync(~0u, p1, off);
    }
    if (lane == 0) {
        float l0 = p0 + s_b2[0], l1 = p1 + s_b2[1];
        float mx = fmaxf(l0, l1);
        float lse = __logf(__expf(l0 - mx) + __expf(l1 - mx)) + mx;
        outp[(size_t)3 * EE + (size_t)w * 2 + 0] = l0 - lse;
        outp[(size_t)3 * EE + (size_t)w * 2 + 1] = l1 - lse;
    }
}

// ---------------- edge classifier, CSR order, bf16 gathers ----------------------
__global__ void k_edge(const uint2* __restrict__ ea2, const uint2* __restrict__ eb2v,
                       const float* __restrict__ eb1, const float* __restrict__ ew2,
                       const float* __restrict__ eb2, float* __restrict__ outp) {
    __shared__ float s_b1[64], s_w2[192], s_b2[3];
    int tid = threadIdx.x;
    if (tid < 64)  s_b1[tid] = eb1[tid];
    if (tid < 192) s_w2[tid] = ew2[tid];
    if (tid < 3)   s_b2[tid] = eb2[tid];
    __syncthreads();

    int gid = blockIdx.x * blockDim.x + tid;
    int p = gid >> 4, sub = tid & 15;
    if (p >= EE) return;
    int r  = g_srcl[p];
    int c  = g_dstl[p];
    int id = g_eidl[p];
    uint2 va = ea2[(size_t)r * 16 + sub];
    uint2 vb = eb2v[(size_t)c * 16 + sub];
    float h[4];
    h[0] = fmaxf(bflo(va.x) + bflo(vb.x) + s_b1[sub * 4 + 0], 0.f);
    h[1] = fmaxf(bfhi(va.x) + bfhi(vb.x) + s_b1[sub * 4 + 1], 0.f);
    h[2] = fmaxf(bflo(va.y) + bflo(vb.y) + s_b1[sub * 4 + 2], 0.f);
    h[3] = fmaxf(bfhi(va.y) + bfhi(vb.y) + s_b1[sub * 4 + 3], 0.f);
    float p0 = 0.f, p1 = 0.f, p2 = 0.f;
#pragma unroll
    for (int i = 0; i < 4; i++) {
        int f = sub * 4 + i;
        p0 += h[i] * s_w2[f * 3 + 0];
        p1 += h[i] * s_w2[f * 3 + 1];
        p2 += h[i] * s_w2[f * 3 + 2];
    }
#pragma unroll
    for (int off = 8; off; off >>= 1) {
        p0 += __shfl_xor_sync(~0u, p0, off);
        p1 += __shfl_xor_sync(~0u, p1, off);
        p2 += __shfl_xor_sync(~0u, p2, off);
    }
    if (sub == 0) {
        float l0 = p0 + s_b2[0], l1 = p1 + s_b2[1], l2 = p2 + s_b2[2];
        float mx = fmaxf(l0, fmaxf(l1, l2));
        float lse = __logf(__expf(l0 - mx) + __expf(l1 - mx) + __expf(l2 - mx)) + mx;
        outp[(size_t)id * 3 + 0] = l0 - lse;
        outp[(size_t)id * 3 + 1] = l1 - lse;
        outp[(size_t)id * 3 + 2] = l2 - lse;
    }
}

// ---------------- host orchestration -------------------------------------------
extern "C" void kernel_launch(void* const* d_in, const int* in_sizes, int n_in,
                              void* d_out, int out_size) {
    const float* x     = (const float*)d_in[0];
    const void*  eidx  = d_in[1];
    const void*  etyp  = d_in[2];
    const float* W1    = (const float*)d_in[3];
    const float* root1 = (const float*)d_in[4];
    const float* b1    = (const float*)d_in[5];
    const float* W2    = (const float*)d_in[6];
    const float* root2 = (const float*)d_in[7];
    const float* b2    = (const float*)d_in[8];
    const float* W3    = (const float*)d_in[9];
    const float* root3 = (const float*)d_in[10];
    const float* b3    = (const float*)d_in[11];
    const float* ln_g  = (const float*)d_in[12];
    const float* ln_b  = (const float*)d_in[13];
    const float* ew1   = (const float*)d_in[14];
    const float* eb1   = (const float*)d_in[15];
    const float* ew2   = (const float*)d_in[16];
    const float* eb2   = (const float*)d_in[17];
    const float* nw1   = (const float*)d_in[18];
    const float* nb1   = (const float*)d_in[19];
    const float* nw2   = (const float*)d_in[20];
    const float* nb2   = (const float*)d_in[21];
    float* out = (float*)d_out;

    float *p_bufa, *p_bufb;
    uint32_t *p_xr, *p_hb, *p_ea, *p_eb, *p_wt1, *p_wt2, *p_wt3, *p_wte;
    cudaGetSymbolAddress((void**)&p_xr,   g_xr);
    cudaGetSymbolAddress((void**)&p_bufa, g_bufa);
    cudaGetSymbolAddress((void**)&p_bufb, g_bufb);
    cudaGetSymbolAddress((void**)&p_hb,   g_hb);
    cudaGetSymbolAddress((void**)&p_ea,   g_ea);
    cudaGetSymbolAddress((void**)&p_eb,   g_eb);
    cudaGetSymbolAddress((void**)&p_wt1,  g_wt1);
    cudaGetSymbolAddress((void**)&p_wt2,  g_wt2);
    cudaGetSymbolAddress((void**)&p_wt3,  g_wt3);
    cudaGetSymbolAddress((void**)&p_wte,  g_wte);

    const int SMEM_F4 = 58368 + 3 * 4 * 6144;   // 132096 B (fp32-A, NT=4)
    const int SMEM_B4 = 30720 + 3 * 4 * 6144;   // 104448 B (bf16-A, NT=4)
    const int SMEM_B2 = 30720 + 3 * 2 * 6144;   //  67584 B (bf16-A, NT=2)
    cudaFuncSetAttribute((const void*)k_mma<4, 0>, cudaFuncAttributeMaxDynamicSharedMemorySize, SMEM_F4);
    cudaFuncSetAttribute((const void*)k_mma<4, 1>, cudaFuncAttributeMaxDynamicSharedMemorySize, SMEM_B4);
    cudaFuncSetAttribute((const void*)k_mma<2, 1>, cudaFuncAttributeMaxDynamicSharedMemorySize, SMEM_B2);

    int tiles = (NN + 127) / 128;            // 391
    int warpNBlocks = (NN * 32 + 255) / 256;
    int packN = 256 * 400 + 8192 + 8192 + 4096;
    int initB = SCANB + (packN + 255) / 256;
    size_t NH32 = (size_t)NN * 32;

    // 1-4: init(zero+detect+pack), convert+count, bsum, layer-1 GEMM (profiled)
    k_init<<<initB, 256>>>((const unsigned int*)eidx, W1, root1, W2, root2, W3, root3, ew1);
    k_convert<<<(EE + 255) / 256, 256>>>(eidx, etyp);
    k_bsum<<<SCANB, 256>>>();
    k_mma<4, 0><<<tiles, 512, SMEM_F4>>>(x, p_wt1, NN, FIN, 400,
                                         p_xr, p_xr + NH32, p_xr + 2 * NH32, p_bufa, b1);

    // 5-7: rest of CSR build
    k_bscan<<<1, 1024>>>();
    k_off<<<SCANB, 256>>>();
    k_scatter<<<(EE + 255) / 256, 256>>>();

    // 8: layer-1 aggregate + relu -> bf16 h1
    k_agg<<<warpNBlocks, 256>>>(p_xr, p_bufa, p_hb);

    // 9-10: layer 2 (A = bf16 h1)
    k_mma<4, 1><<<tiles, 512, SMEM_B4>>>(p_hb, p_wt2, NN, 64, 32,
                                         p_xr, p_xr + NH32, p_xr + 2 * NH32, p_bufb, b2);
    k_agg<<<warpNBlocks, 256>>>(p_xr, p_bufb, p_hb);

    // 11-12: layer 3 + fused agg/LN/node-head (x3 bf16 -> g_hb)
    k_mma<4, 1><<<tiles, 512, SMEM_B4>>>(p_hb, p_wt3, NN, 64, 32,
                                         p_xr, p_xr + NH32, p_xr + 2 * NH32, p_bufa, b3);
    k_agg_ln_node<<<warpNBlocks, 256>>>(p_xr, p_bufa, p_hb, ln_g, ln_b,
                                        nw1, nb1, nw2, nb2, out);

    // 13-14: edge head (A = x3 bf16)
    k_mma<2, 1><<<tiles, 512, SMEM_B2>>>(p_hb, p_wte, NN, 64, 32,
                                         p_ea, p_eb, nullptr, nullptr, nullptr);
    k_edge<<<(EE * 16 + 255) / 256, 256>>>((const uint2*)p_ea, (const uint2*)p_eb,
                                           eb1, ew2, eb2, out);
}

// round 13
// speedup vs baseline: 1.1075x; 1.0805x over previous
#include <cuda_runtime.h>
#include <math.h>
#include <stdint.h>

#define NN 50000
#define EE 1600000
#define FIN 770
#define RR 3
#define SEG (RR * NN)               // 150000
#define SCANB ((SEG + 255) / 256)   // 586

// ---------------- scratch ------------------------------------------------------
__device__ uint32_t g_xr[(size_t)RR * NN * 32];   // bf16x2 rows (64 feat = 32 u32)
__device__ float    g_bufa[(size_t)NN * 64];      // fp32 root results
__device__ float    g_bufb[(size_t)NN * 64];
__device__ uint32_t g_hb[(size_t)NN * 32];        // bf16x2 activations (h1/h2/x3)
__device__ uint32_t g_ea[(size_t)NN * 32];
__device__ uint32_t g_eb[(size_t)NN * 32];
__device__ float g_invc[SEG];
__device__ int   g_cnt[SEG];
__device__ int   g_off[SEG];
__device__ int   g_fill[SEG];
__device__ int   g_bsum[1024];
__device__ int   g_srcl[EE];
__device__ int   g_dstl[EE];
__device__ int   g_eidl[EE];
__device__ int   g_row[EE];
__device__ int   g_col[EE];
__device__ int   g_et[EE];
__device__ int   g_is64;
__device__ uint32_t g_wt1[256 * 400];   // bf16x2 pairs, [N][Kp2]
__device__ uint32_t g_wt2[256 * 32];
__device__ uint32_t g_wt3[256 * 32];
__device__ uint32_t g_wte[128 * 32];

// ---------------- helpers ------------------------------------------------------
__device__ __forceinline__ uint32_t smem_u32(const void* p) {
    uint32_t a;
    asm("{ .reg .u64 t; cvta.to.shared.u64 t, %1; cvt.u32.u64 %0, t; }" : "=r"(a) : "l"(p));
    return a;
}
__device__ __forceinline__ void cp16(uint32_t dst, const void* src, int sz) {
    asm volatile("cp.async.cg.shared.global [%0], [%1], 16, %2;"
                 :: "r"(dst), "l"(src), "r"(sz) : "memory");
}
__device__ __forceinline__ void cp8(uint32_t dst, const void* src, int sz) {
    asm volatile("cp.async.ca.shared.global [%0], [%1], 8, %2;"
                 :: "r"(dst), "l"(src), "r"(sz) : "memory");
}
__device__ __forceinline__ uint32_t f2bf2(float lo, float hi) {
    uint32_t r;
    asm("cvt.rn.bf16x2.f32 %0, %1, %2;" : "=r"(r) : "f"(hi), "f"(lo));
    return r;
}
__device__ __forceinline__ float bflo(uint32_t v) { return __uint_as_float(v << 16); }
__device__ __forceinline__ float bfhi(uint32_t v) { return __uint_as_float(v & 0xFFFF0000u); }
__device__ __forceinline__ void mma16(float* c, const uint32_t* a, uint32_t b0, uint32_t b1) {
    asm volatile(
        "mma.sync.aligned.m16n8k16.row.col.f32.bf16.bf16.f32 "
        "{%0,%1,%2,%3}, {%4,%5,%6,%7}, {%8,%9}, {%0,%1,%2,%3};"
        : "+f"(c[0]), "+f"(c[1]), "+f"(c[2]), "+f"(c[3])
        : "r"(a[0]), "r"(a[1]), "r"(a[2]), "r"(a[3]), "r"(b0), "r"(b1));
}

// ---------------- launch 1: fused detect+zero + weight pack ---------------------
__global__ void k_init(const unsigned int* __restrict__ ei,
                       const float* __restrict__ W1, const float* __restrict__ root1,
                       const float* __restrict__ W2, const float* __restrict__ root2,
                       const float* __restrict__ W3, const float* __restrict__ root3,
                       const float* __restrict__ ew1) {
    int b = blockIdx.x;
    if (b < SCANB) {
        int i = b * 256 + threadIdx.x;
        if (i < SEG) { g_cnt[i] = 0; g_fill[i] = 0; }
        if (i == 0) {
            int is64 = 1;
            for (int j = 0; j < 64; j++)
                if (ei[2 * j + 1] != 0u) { is64 = 0; break; }
            g_is64 = is64;
        }
        return;
    }
    int i = (b - SCANB) * 256 + threadIdx.x;
    if (i < 256 * 400) {                                 // wt1  [256][400]
        int n = i / 400, s = i % 400;
        int jj = s & 7, k0 = (s >> 3) * 16 + (jj >> 1) * 2 + (jj & 1) * 8;
        float lo = 0.f, hi = 0.f;
        if (n < 192) {
            if (k0 < FIN)     lo = W1[(size_t)(n >> 6) * FIN * 64 + (size_t)k0 * 64 + (n & 63)];
            if (k0 + 1 < FIN) hi = W1[(size_t)(n >> 6) * FIN * 64 + (size_t)(k0 + 1) * 64 + (n & 63)];
        } else {
            if (k0 < FIN)     lo = root1[(size_t)k0 * 64 + (n - 192)];
            if (k0 + 1 < FIN) hi = root1[(size_t)(k0 + 1) * 64 + (n - 192)];
        }
        g_wt1[i] = f2bf2(lo, hi);
        return;
    }
    int j = i - 256 * 400;
    if (j < 8192) {                                      // wt2 [256][32]
        int n = j >> 5, s = j & 31;
        int jj = s & 7, k0 = (s >> 3) * 16 + (jj >> 1) * 2 + (jj & 1) * 8;
        float lo, hi;
        if (n < 192) {
            lo = W2[(n >> 6) * 4096 + k0 * 64 + (n & 63)];
            hi = W2[(n >> 6) * 4096 + (k0 + 1) * 64 + (n & 63)];
        } else {
            lo = root2[k0 * 64 + (n - 192)];
            hi = root2[(k0 + 1) * 64 + (n - 192)];
        }
        g_wt2[j] = f2bf2(lo, hi);
        return;
    }
    j -= 8192;
    if (j < 8192) {                                      // wt3
        int n = j >> 5, s = j & 31;
        int jj = s & 7, k0 = (s >> 3) * 16 + (jj >> 1) * 2 + (jj & 1) * 8;
        float lo, hi;
        if (n < 192) {
            lo = W3[(n >> 6) * 4096 + k0 * 64 + (n & 63)];
            hi = W3[(n >> 6) * 4096 + (k0 + 1) * 64 + (n & 63)];
        } else {
            lo = root3[k0 * 64 + (n - 192)];
            hi = root3[(k0 + 1) * 64 + (n - 192)];
        }
        g_wt3[j] = f2bf2(lo, hi);
        return;
    }
    j -= 8192;
    if (j < 4096) {                                      // wte [128][32]
        int n = j >> 5, s = j & 31;
        int jj = s & 7, k0 = (s >> 3) * 16 + (jj >> 1) * 2 + (jj & 1) * 8;
        float lo, hi;
        if (n < 64) { lo = ew1[k0 * 64 + n];               hi = ew1[(k0 + 1) * 64 + n]; }
        else        { lo = ew1[(64 + k0) * 64 + (n - 64)]; hi = ew1[(64 + k0 + 1) * 64 + (n - 64)]; }
        g_wte[j] = f2bf2(lo, hi);
    }
}

// ---------------- launch 2: convert + degree count ------------------------------
__global__ void k_convert(const void* __restrict__ ei, const void* __restrict__ et) {
    int i = blockIdx.x * blockDim.x + threadIdx.x;
    if (i >= EE) return;
    int r, c, t;
    if (g_is64) {
        const long long* p = (const long long*)ei;
        r = (int)p[i];
        c = (int)p[EE + i];
        t = (int)((const long long*)et)[i];
    } else {
        const int* p = (const int*)ei;
        r = p[i];
        c = p[EE + i];
        t = ((const int*)et)[i];
    }
    g_row[i] = r; g_col[i] = c; g_et[i] = t;
    atomicAdd(&g_cnt[t * NN + c], 1);
}

// ---------------- CSR build ------------------------------------------------------
__global__ void k_bsum() {
    __shared__ int sh[256];
    int i = blockIdx.x * 256 + threadIdx.x;
    sh[threadIdx.x] = (i < SEG) ? g_cnt[i] : 0;
    __syncthreads();
    for (int o = 128; o > 0; o >>= 1) {
        if (threadIdx.x < o) sh[threadIdx.x] += sh[threadIdx.x + o];
        __syncthreads();
    }
    if (threadIdx.x == 0) g_bsum[blockIdx.x] = sh[0];
}
__global__ void k_bscan() {
    __shared__ int sh[1024];
    int tid = threadIdx.x;
    int v = (tid < SCANB) ? g_bsum[tid] : 0;
    sh[tid] = v;
    __syncthreads();
    for (int o = 1; o < 1024; o <<= 1) {
        int t = (tid >= o) ? sh[tid - o] : 0;
        __syncthreads();
        sh[tid] += t;
        __syncthreads();
    }
    if (tid < SCANB) g_bsum[tid] = sh[tid] - v;
}
__global__ void k_off() {
    __shared__ int sh[256];
    int tid = threadIdx.x;
    int i = blockIdx.x * 256 + tid;
    int v = (i < SEG) ? g_cnt[i] : 0;
    sh[tid] = v;
    __syncthreads();
    for (int o = 1; o < 256; o <<= 1) {
        int t = (tid >= o) ? sh[tid - o] : 0;
        __syncthreads();
        sh[tid] += t;
        __syncthreads();
    }
    if (i < SEG) {
        g_off[i] = sh[tid] - v + g_bsum[blockIdx.x];
        g_invc[i] = 1.0f / (float)(v > 0 ? v : 1);
    }
}
__global__ void k_scatter() {
    int e = blockIdx.x * blockDim.x + threadIdx.x;
    if (e >= EE) return;
    int c = g_col[e];
    int idx = g_et[e] * NN + c;
    int pos = g_off[idx] + atomicAdd(&g_fill[idx], 1);
    g_srcl[pos] = g_row[e];
    g_dstl[pos] = c;
    g_eidl[pos] = e;
}

// ---------------- GEMM: A (fp32 or bf16x2) @ bf16[N,Kp2]^T, N = NT*64 -----------
// 512 threads / 16 warps; MT = NT/2 row-tiles of 16 per warp; 3-stage cp.async.
// ABF=0: A fp32, smem rows 160B stride, plain cp8 loads (round-9 verified path).
// ABF=1: A bf16x2, smem rows 80B, ldmatrix.
template<int NT, int ABF>
__device__ __forceinline__ void issue_chunk(const void* __restrict__ X,
                                            const uint32_t* __restrict__ Wt,
                                            int M, int K, int Kp2, int m0, int c, int buf,
                                            uint32_t sb) {
    int tid = threadIdx.x;
    uint32_t bb = sb + (ABF ? 30720u : 61440u) + (uint32_t)buf * (uint32_t)(NT * 6144);
    if (ABF) {
        uint32_t ab = sb + (uint32_t)buf * 10240u;
        int row = tid >> 2, j = tid & 3;          // 512 units: 128 rows x 4 of 16B
        int ok = (m0 + row) < M;
        const uint32_t* src = (const uint32_t*)X + (size_t)(m0 + row) * Kp2 + c * 16 + j * 4;
        cp16(ab + row * 80 + j * 16, ok ? (const void*)src : X, ok ? 16 : 0);
    } else {
        uint32_t ab = sb + (uint32_t)buf * 20480u;
        int k0 = c * 32;
#pragma unroll
        for (int i = 0; i < 4; i++) {
            int u = i * 512 + tid;                // 2048 units: 128 rows x 16 of 8B
            int row = u >> 4, j = u & 15;
            int kk = k0 + j * 2;
            int ok = ((m0 + row) < M) && (kk < K);
            const float* src = ok ? ((const float*)X + (size_t)(m0 + row) * K + kk)
                                  : (const float*)X;
            int sz = ok ? ((K - kk >= 2) ? 8 : 4) : 0;
            cp8(ab + row * 160 + j * 8, src, sz);
        }
    }
#pragma unroll
    for (int i = 0; i < NT / 2; i++) {
        int u = i * 512 + tid;                    // NT*64 rows x 4 units of 16B
        int r2 = u >> 2, j2 = u & 3;
        cp16(bb + r2 * 96 + j2 * 16, Wt + (size_t)r2 * Kp2 + c * 16 + j2 * 4, 16);
    }
    asm volatile("cp.async.commit_group;" ::: "memory");
}

template<int NT, int ABF>
__global__ __launch_bounds__(512, 1) void k_mma(
    const void* __restrict__ X, const uint32_t* __restrict__ Wt,
    int M, int K, int Kp2,
    uint32_t* __restrict__ ob0, uint32_t* __restrict__ ob1,
    uint32_t* __restrict__ ob2, float* __restrict__ o3fp,
    const float* __restrict__ bias3)
{
    extern __shared__ float smf[];
    const uint32_t* smu = (const uint32_t*)smf;
    uint32_t sb = smem_u32(smf);
    const int MT = NT / 2;
    int tid = threadIdx.x, wid = tid >> 5, lane = tid & 31;
    int g = lane >> 2, tig = lane & 3;
    int wn = wid % NT, wm = wid / NT;
    int rowbase = wm * MT * 16;
    int m0 = blockIdx.x * 128;
    int NC = (K + 31) / 32;

    float acc[MT][8][4];
#pragma unroll
    for (int mt = 0; mt < MT; mt++)
#pragma unroll
        for (int nt = 0; nt < 8; nt++)
#pragma unroll
            for (int q = 0; q < 4; q++) acc[mt][nt][q] = 0.f;

    issue_chunk<NT, ABF>(X, Wt, M, K, Kp2, m0, 0, 0, sb);
    if (NC > 1) issue_chunk<NT, ABF>(X, Wt, M, K, Kp2, m0, 1, 1, sb);

    int buf = 0;
    for (int c = 0; c < NC; c++) {
        if (c + 2 < NC) {
            int b2 = buf + 2; if (b2 >= 3) b2 -= 3;
            issue_chunk<NT, ABF>(X, Wt, M, K, Kp2, m0, c + 2, b2, sb);
            asm volatile("cp.async.wait_group 2;" ::: "memory");
        } else if (c + 1 < NC) {
            asm volatile("cp.async.wait_group 1;" ::: "memory");
        } else {
            asm volatile("cp.async.wait_group 0;" ::: "memory");
        }
        __syncthreads();

        int bf = (ABF ? 7680 : 15360) + buf * (NT * 1536);   // u32 index
#pragma unroll
        for (int st = 0; st < 2; st++) {
            uint32_t A[MT][4];
#pragma unroll
            for (int mt = 0; mt < MT; mt++) {
                if (ABF) {
                    uint32_t addr = sb + (uint32_t)buf * 10240u
                        + (uint32_t)((rowbase + mt * 16 + (lane & 15)) * 80
                                     + (lane >> 4) * 16 + st * 32);
                    asm volatile(
                        "ldmatrix.sync.aligned.m8n8.x4.shared.b16 {%0,%1,%2,%3}, [%4];"
                        : "=r"(A[mt][0]), "=r"(A[mt][1]), "=r"(A[mt][2]), "=r"(A[mt][3])
                        : "r"(addr));
                } else {
                    int af = buf * 5120;                     // u32 per stage
                    int base = af + (rowbase + mt * 16 + g) * 40 + st * 16 + 2 * tig;
                    float2 x0 = *(const float2*)&smf[base];
                    float2 x1 = *(const float2*)&smf[base + 8 * 40];
                    float2 x2 = *(const float2*)&smf[base + 8];
                    float2 x3 = *(const float2*)&smf[base + 8 * 40 + 8];
                    A[mt][0] = f2bf2(x0.x, x0.y);
                    A[mt][1] = f2bf2(x1.x, x1.y);
                    A[mt][2] = f2bf2(x2.x, x2.y);
                    A[mt][3] = f2bf2(x3.x, x3.y);
                }
            }
#pragma unroll
            for (int nt = 0; nt < 8; nt++) {
                int nb = bf + (wn * 64 + nt * 8 + g) * 24 + st * 8 + tig * 2;
                uint2 bv = *(const uint2*)&smu[nb];
#pragma unroll
                for (int mt = 0; mt < MT; mt++)
                    mma16(acc[mt][nt], A[mt], bv.x, bv.y);
            }
        }
        __syncthreads();
        buf = (buf + 1 == 3) ? 0 : buf + 1;
    }

    bool fp = (wn == NT - 1) && (o3fp != nullptr);
    uint32_t* ob = (wn == 0) ? ob0 : ((wn == 1) ? ob1 : ob2);
#pragma unroll
    for (int mt = 0; mt < MT; mt++) {
        int mA = m0 + rowbase + mt * 16 + g;
        int mB = mA + 8;
#pragma unroll
        for (int nt = 0; nt < 8; nt++) {
            int col = nt * 8 + tig * 2;
            float c0 = acc[mt][nt][0], c1 = acc[mt][nt][1];
            float c2 = acc[mt][nt][2], c3 = acc[mt][nt][3];
            if (fp) {
                float bb0 = bias3[col], bb1 = bias3[col + 1];
                c0 += bb0; c1 += bb1; c2 += bb0; c3 += bb1;
                if (mA < M) *(float2*)(o3fp + (size_t)mA * 64 + col) = make_float2(c0, c1);
                if (mB < M) *(float2*)(o3fp + (size_t)mB * 64 + col) = make_float2(c2, c3);
            } else {
                if (mA < M) ob[(size_t)mA * 32 + (col >> 1)] = f2bf2(c0, c1);
                if (mB < M) ob[(size_t)mB * 32 + (col >> 1)] = f2bf2(c2, c3);
            }
        }
    }
}

// ---------------- CSR aggregation core: bf16 gathers (feat 2l, 2l+1) ------------
__device__ __forceinline__ void agg_core(const uint32_t* __restrict__ xr, int w, int lane,
                                         float& a0, float& a1) {
#pragma unroll
    for (int r = 0; r < RR; r++) {
        int idx = r * NN + w;
        int beg = g_off[idx], n = g_cnt[idx];
        const uint32_t* xrr = xr + (size_t)r * NN * 32;
        float s0 = 0.f, s1 = 0.f;
        for (int b = 0; b < n; b += 32) {
            int src = (b + lane < n) ? g_srcl[beg + b + lane] : 0;
            int m = min(32, n - b);
            int j = 0;
            for (; j + 8 <= m; j += 8) {
                uint32_t v[8];
#pragma unroll
                for (int q = 0; q < 8; q++)
                    v[q] = xrr[(size_t)__shfl_sync(~0u, src, j + q) * 32 + lane];
                float t0 = 0.f, t1 = 0.f;
#pragma unroll
                for (int q = 0; q < 8; q++) {
                    t0 += bflo(v[q]);
                    t1 += bfhi(v[q]);
                }
                s0 += t0; s1 += t1;
            }
            for (; j + 4 <= m; j += 4) {
                uint32_t v[4];
#pragma unroll
                for (int q = 0; q < 4; q++)
                    v[q] = xrr[(size_t)__shfl_sync(~0u, src, j + q) * 32 + lane];
#pragma unroll
                for (int q = 0; q < 4; q++) {
                    s0 += bflo(v[q]);
                    s1 += bfhi(v[q]);
                }
            }
            for (; j < m; j++) {
                uint32_t v = xrr[(size_t)__shfl_sync(~0u, src, j) * 32 + lane];
                s0 += bflo(v);
                s1 += bfhi(v);
            }
        }
        float ic = g_invc[idx];
        a0 += s0 * ic;
        a1 += s1 * ic;
    }
}

// agg + relu -> bf16x2 activation buffer
__global__ void k_agg(const uint32_t* __restrict__ xr, const float* __restrict__ io,
                      uint32_t* __restrict__ outb) {
    int w = (blockIdx.x * blockDim.x + threadIdx.x) >> 5;
    int lane = threadIdx.x & 31;
    if (w >= NN) return;
    float a0 = 0.f, a1 = 0.f;
    agg_core(xr, w, lane, a0, a1);
    float2 cur = *(const float2*)&io[(size_t)w * 64 + 2 * lane];
    float v0 = fmaxf(cur.x + a0, 0.f);
    float v1 = fmaxf(cur.y + a1, 0.f);
    outb[(size_t)w * 32 + lane] = f2bf2(v0, v1);
}

// ---------------- fused: agg(layer3) + LayerNorm + node head --------------------
__global__ void k_agg_ln_node(const uint32_t* __restrict__ xr, const float* __restrict__ io,
                              uint32_t* __restrict__ x3out,
                              const float* __restrict__ gg, const float* __restrict__ bb,
                              const float* __restrict__ nw1, const float* __restrict__ nb1,
                              const float* __restrict__ nw2, const float* __restrict__ nb2,
                              float* __restrict__ outp) {
    __shared__ float s_w1[64 * 32];
    __shared__ float s_b1[32], s_w2[64], s_b2[2], s_g[64], s_bb[64];
    int tid = threadIdx.x;
    for (int i = tid; i < 2048; i += blockDim.x) s_w1[i] = nw1[i];
    if (tid < 32) s_b1[tid] = nb1[tid];
    if (tid < 64) { s_w2[tid] = nw2[tid]; s_g[tid] = gg[tid]; s_bb[tid] = bb[tid]; }
    if (tid < 2)  s_b2[tid] = nb2[tid];
    __syncthreads();

    int w = (blockIdx.x * blockDim.x + tid) >> 5;
    int lane = tid & 31;
    if (w >= NN) return;
    float a0 = 0.f, a1 = 0.f;
    agg_core(xr, w, lane, a0, a1);
    float2 cur = *(const float2*)&io[(size_t)w * 64 + 2 * lane];
    float v0 = cur.x + a0;
    float v1 = cur.y + a1;

    float s = v0 + v1;
#pragma unroll
    for (int off = 16; off; off >>= 1) s += __shfl_xor_sync(~0u, s, off);
    float mu = s * (1.f / 64.f);
    float d0 = v0 - mu, d1 = v1 - mu;
    float q = d0 * d0 + d1 * d1;
#pragma unroll
    for (int off = 16; off; off >>= 1) q += __shfl_xor_sync(~0u, q, off);
    float rs = rsqrtf(q * (1.f / 64.f) + 1e-5f);
    float xa = d0 * rs * s_g[2 * lane]     + s_bb[2 * lane];
    float xb = d1 * rs * s_g[2 * lane + 1] + s_bb[2 * lane + 1];
    x3out[(size_t)w * 32 + lane] = f2bf2(xa, xb);

    float acc = s_b1[lane];
#pragma unroll
    for (int k = 0; k < 32; k++) {
        float x0 = __shfl_sync(~0u, xa, k);
        float x1 = __shfl_sync(~0u, xb, k);
        acc += x0 * s_w1[(2 * k) * 32 + lane] + x1 * s_w1[(2 * k + 1) * 32 + lane];
    }
    float nh = fmaxf(acc, 0.f);
    float p0 = nh * s_w2[lane * 2 + 0];
    float p1 = nh * s_w2[lane * 2 + 1];
#pragma unroll
    for (int off = 16; off; off >>= 1) {
        p0 += __shfl_xor_sync(~0u, p0, off);
        p1 += __shfl_xor_sync(~0u, p1, off);
    }
    if (lane == 0) {
        float l0 = p0 + s_b2[0], l1 = p1 + s_b2[1];
        float mx = fmaxf(l0, l1);
        float lse = __logf(__expf(l0 - mx) + __expf(l1 - mx)) + mx;
        outp[(size_t)3 * EE + (size_t)w * 2 + 0] = l0 - lse;
        outp[(size_t)3 * EE + (size_t)w * 2 + 1] = l1 - lse;
    }
}

// ---------------- edge classifier, CSR order, 8 lanes/edge, uint4 gathers -------
__global__ void k_edge(const uint4* __restrict__ ea4, const uint4* __restrict__ eb4,
                       const float* __restrict__ eb1, const float* __restrict__ ew2,
                       const float* __restrict__ eb2, float* __restrict__ outp) {
    __shared__ float s_b1[64], s_w2[192], s_b2[3];
    int tid = threadIdx.x;
    if (tid < 64)  s_b1[tid] = eb1[tid];
    if (tid < 192) s_w2[tid] = ew2[tid];
    if (tid < 3)   s_b2[tid] = eb2[tid];
    __syncthreads();

    int gid = blockIdx.x * blockDim.x + tid;
    int p = gid >> 3, sub = tid & 7;
    if (p >= EE) return;
    int r  = g_srcl[p];
    int c  = g_dstl[p];
    int id = g_eidl[p];
    uint4 va = ea4[(size_t)r * 8 + sub];     // feats 8sub..8sub+7
    uint4 vb = eb4[(size_t)c * 8 + sub];
    float h[8];
    h[0] = fmaxf(bflo(va.x) + bflo(vb.x) + s_b1[sub * 8 + 0], 0.f);
    h[1] = fmaxf(bfhi(va.x) + bfhi(vb.x) + s_b1[sub * 8 + 1], 0.f);
    h[2] = fmaxf(bflo(va.y) + bflo(vb.y) + s_b1[sub * 8 + 2], 0.f);
    h[3] = fmaxf(bfhi(va.y) + bfhi(vb.y) + s_b1[sub * 8 + 3], 0.f);
    h[4] = fmaxf(bflo(va.z) + bflo(vb.z) + s_b1[sub * 8 + 4], 0.f);
    h[5] = fmaxf(bfhi(va.z) + bfhi(vb.z) + s_b1[sub * 8 + 5], 0.f);
    h[6] = fmaxf(bflo(va.w) + bflo(vb.w) + s_b1[sub * 8 + 6], 0.f);
    h[7] = fmaxf(bfhi(va.w) + bfhi(vb.w) + s_b1[sub * 8 + 7], 0.f);
    float p0 = 0.f, p1 = 0.f, p2 = 0.f;
#pragma unroll
    for (int i = 0; i < 8; i++) {
        int f = sub * 8 + i;
        p0 += h[i] * s_w2[f * 3 + 0];
        p1 += h[i] * s_w2[f * 3 + 1];
        p2 += h[i] * s_w2[f * 3 + 2];
    }
#pragma unroll
    for (int off = 4; off; off >>= 1) {
        p0 += __shfl_xor_sync(~0u, p0, off);
        p1 += __shfl_xor_sync(~0u, p1, off);
        p2 += __shfl_xor_sync(~0u, p2, off);
    }
    if (sub == 0) {
        float l0 = p0 + s_b2[0], l1 = p1 + s_b2[1], l2 = p2 + s_b2[2];
        float mx = fmaxf(l0, fmaxf(l1, l2));
        float lse = __logf(__expf(l0 - mx) + __expf(l1 - mx) + __expf(l2 - mx)) + mx;
        outp[(size_t)id * 3 + 0] = l0 - lse;
        outp[(size_t)id * 3 + 1] = l1 - lse;
        outp[(size_t)id * 3 + 2] = l2 - lse;
    }
}

// ---------------- host orchestration -------------------------------------------
extern "C" void kernel_launch(void* const* d_in, const int* in_sizes, int n_in,
                              void* d_out, int out_size) {
    const float* x     = (const float*)d_in[0];
    const void*  eidx  = d_in[1];
    const void*  etyp  = d_in[2];
    const float* W1    = (const float*)d_in[3];
    const float* root1 = (const float*)d_in[4];
    const float* b1    = (const float*)d_in[5];
    const float* W2    = (const float*)d_in[6];
    const float* root2 = (const float*)d_in[7];
    const float* b2    = (const float*)d_in[8];
    const float* W3    = (const float*)d_in[9];
    const float* root3 = (const float*)d_in[10];
    const float* b3    = (const float*)d_in[11];
    const float* ln_g  = (const float*)d_in[12];
    const float* ln_b  = (const float*)d_in[13];
    const float* ew1   = (const float*)d_in[14];
    const float* eb1   = (const float*)d_in[15];
    const float* ew2   = (const float*)d_in[16];
    const float* eb2   = (const float*)d_in[17];
    const float* nw1   = (const float*)d_in[18];
    const float* nb1   = (const float*)d_in[19];
    const float* nw2   = (const float*)d_in[20];
    const float* nb2   = (const float*)d_in[21];
    float* out = (float*)d_out;

    float *p_bufa, *p_bufb;
    uint32_t *p_xr, *p_hb, *p_ea, *p_eb, *p_wt1, *p_wt2, *p_wt3, *p_wte;
    cudaGetSymbolAddress((void**)&p_xr,   g_xr);
    cudaGetSymbolAddress((void**)&p_bufa, g_bufa);
    cudaGetSymbolAddress((void**)&p_bufb, g_bufb);
    cudaGetSymbolAddress((void**)&p_hb,   g_hb);
    cudaGetSymbolAddress((void**)&p_ea,   g_ea);
    cudaGetSymbolAddress((void**)&p_eb,   g_eb);
    cudaGetSymbolAddress((void**)&p_wt1,  g_wt1);
    cudaGetSymbolAddress((void**)&p_wt2,  g_wt2);
    cudaGetSymbolAddress((void**)&p_wt3,  g_wt3);
    cudaGetSymbolAddress((void**)&p_wte,  g_wte);

    const int SMEM_F4 = 61440 + 3 * 4 * 6144;   // 135168 B (fp32-A, NT=4)
    const int SMEM_B4 = 30720 + 3 * 4 * 6144;   // 104448 B (bf16-A, NT=4)
    const int SMEM_B2 = 30720 + 3 * 2 * 6144;   //  67584 B (bf16-A, NT=2)
    cudaFuncSetAttribute((const void*)k_mma<4, 0>, cudaFuncAttributeMaxDynamicSharedMemorySize, SMEM_F4);
    cudaFuncSetAttribute((const void*)k_mma<4, 1>, cudaFuncAttributeMaxDynamicSharedMemorySize, SMEM_B4);
    cudaFuncSetAttribute((const void*)k_mma<2, 1>, cudaFuncAttributeMaxDynamicSharedMemorySize, SMEM_B2);

    int tiles = (NN + 127) / 128;            // 391
    int warpNBlocks = (NN * 32 + 255) / 256;
    int packN = 256 * 400 + 8192 + 8192 + 4096;
    int initB = SCANB + (packN + 255) / 256;
    size_t NH32 = (size_t)NN * 32;

    // 1-4: init(zero+detect+pack), convert+count, bsum, layer-1 GEMM (profiled)
    k_init<<<initB, 256>>>((const unsigned int*)eidx, W1, root1, W2, root2, W3, root3, ew1);
    k_convert<<<(EE + 255) / 256, 256>>>(eidx, etyp);
    k_bsum<<<SCANB, 256>>>();
    k_mma<4, 0><<<tiles, 512, SMEM_F4>>>(x, p_wt1, NN, FIN, 400,
                                         p_xr, p_xr + NH32, p_xr + 2 * NH32, p_bufa, b1);

    // 5-7: rest of CSR build
    k_bscan<<<1, 1024>>>();
    k_off<<<SCANB, 256>>>();
    k_scatter<<<(EE + 255) / 256, 256>>>();

    // 8: layer-1 aggregate + relu -> bf16 h1
    k_agg<<<warpNBlocks, 256>>>(p_xr, p_bufa, p_hb);

    // 9-10: layer 2 (A = bf16 h1)
    k_mma<4, 1><<<tiles, 512, SMEM_B4>>>(p_hb, p_wt2, NN, 64, 32,
                                         p_xr, p_xr + NH32, p_xr + 2 * NH32, p_bufb, b2);
    k_agg<<<warpNBlocks, 256>>>(p_xr, p_bufb, p_hb);

    // 11-12: layer 3 + fused agg/LN/node-head (x3 bf16 -> g_hb)
    k_mma<4, 1><<<tiles, 512, SMEM_B4>>>(p_hb, p_wt3, NN, 64, 32,
                                         p_xr, p_xr + NH32, p_xr + 2 * NH32, p_bufa, b3);
    k_agg_ln_node<<<warpNBlocks, 256>>>(p_xr, p_bufa, p_hb, ln_g, ln_b,
                                        nw1, nb1, nw2, nb2, out);

    // 13-14: edge head (A = x3 bf16)
    k_mma<2, 1><<<tiles, 512, SMEM_B2>>>(p_hb, p_wte, NN, 64, 32,
                                         p_ea, p_eb, nullptr, nullptr, nullptr);
    k_edge<<<(EE * 8 + 255) / 256, 256>>>((const uint4*)p_ea, (const uint4*)p_eb,
                                          eb1, ew2, eb2, out);
}

// round 14
// speedup vs baseline: 1.1578x; 1.0454x over previous
#include <cuda_runtime.h>
#include <math.h>
#include <stdint.h>

#define NN 50000
#define EE 1600000
#define FIN 770
#define RR 3
#define SEG (RR * NN)               // 150000
#define SCANB ((SEG + 255) / 256)   // 586

// ---------------- scratch ------------------------------------------------------
__device__ uint32_t g_xr[(size_t)RR * NN * 32];   // bf16x2 rows (64 feat = 32 u32)
__device__ float    g_bufa[(size_t)NN * 64];      // fp32 root results
__device__ float    g_bufb[(size_t)NN * 64];
__device__ uint32_t g_hb[(size_t)NN * 32];        // bf16x2 activations (h1/h2/x3)
__device__ uint32_t g_ea[(size_t)NN * 32];
__device__ uint32_t g_eb[(size_t)NN * 32];
__device__ float g_invc[SEG];
__device__ int   g_cnt[SEG];
__device__ int   g_off[SEG];
__device__ int   g_fill[SEG];
__device__ int   g_gctr;
__device__ uint32_t g_sd[EE];       // src | dst<<16 (edge order)
__device__ uint8_t  g_et8[EE];
__device__ uint32_t g_sdl[EE];      // packed, CSR order
__device__ int      g_eidl[EE];
__device__ int   g_is64;
__device__ uint32_t g_wt1[256 * 400];   // bf16x2 pairs, [N][Kp2]
__device__ uint32_t g_wt2[256 * 32];
__device__ uint32_t g_wt3[256 * 32];
__device__ uint32_t g_wte[128 * 32];

// ---------------- helpers ------------------------------------------------------
__device__ __forceinline__ uint32_t smem_u32(const void* p) {
    uint32_t a;
    asm("{ .reg .u64 t; cvta.to.shared.u64 t, %1; cvt.u32.u64 %0, t; }" : "=r"(a) : "l"(p));
    return a;
}
__device__ __forceinline__ void cp16(uint32_t dst, const void* src, int sz) {
    asm volatile("cp.async.cg.shared.global [%0], [%1], 16, %2;"
                 :: "r"(dst), "l"(src), "r"(sz) : "memory");
}
__device__ __forceinline__ void cp8(uint32_t dst, const void* src, int sz) {
    asm volatile("cp.async.ca.shared.global [%0], [%1], 8, %2;"
                 :: "r"(dst), "l"(src), "r"(sz) : "memory");
}
__device__ __forceinline__ uint32_t f2bf2(float lo, float hi) {
    uint32_t r;
    asm("cvt.rn.bf16x2.f32 %0, %1, %2;" : "=r"(r) : "f"(hi), "f"(lo));
    return r;
}
__device__ __forceinline__ float bflo(uint32_t v) { return __uint_as_float(v << 16); }
__device__ __forceinline__ float bfhi(uint32_t v) { return __uint_as_float(v & 0xFFFF0000u); }
__device__ __forceinline__ void mma16(float* c, const uint32_t* a, uint32_t b0, uint32_t b1) {
    asm volatile(
        "mma.sync.aligned.m16n8k16.row.col.f32.bf16.bf16.f32 "
        "{%0,%1,%2,%3}, {%4,%5,%6,%7}, {%8,%9}, {%0,%1,%2,%3};"
        : "+f"(c[0]), "+f"(c[1]), "+f"(c[2]), "+f"(c[3])
        : "r"(a[0]), "r"(a[1]), "r"(a[2]), "r"(a[3]), "r"(b0), "r"(b1));
}

// ---------------- launch 1: fused detect+zero + weight pack ---------------------
__global__ void k_init(const unsigned int* __restrict__ ei,
                       const float* __restrict__ W1, const float* __restrict__ root1,
                       const float* __restrict__ W2, const float* __restrict__ root2,
                       const float* __restrict__ W3, const float* __restrict__ root3,
                       const float* __restrict__ ew1) {
    int b = blockIdx.x;
    if (b < SCANB) {
        int i = b * 256 + threadIdx.x;
        if (i < SEG) { g_cnt[i] = 0; g_fill[i] = 0; }
        if (i == 0) {
            g_gctr = 0;
            int is64 = 1;
            for (int j = 0; j < 64; j++)
                if (ei[2 * j + 1] != 0u) { is64 = 0; break; }
            g_is64 = is64;
        }
        return;
    }
    int i = (b - SCANB) * 256 + threadIdx.x;
    if (i < 256 * 400) {                                 // wt1  [256][400]
        int n = i / 400, s = i % 400;
        int jj = s & 7, k0 = (s >> 3) * 16 + (jj >> 1) * 2 + (jj & 1) * 8;
        float lo = 0.f, hi = 0.f;
        if (n < 192) {
            if (k0 < FIN)     lo = W1[(size_t)(n >> 6) * FIN * 64 + (size_t)k0 * 64 + (n & 63)];
            if (k0 + 1 < FIN) hi = W1[(size_t)(n >> 6) * FIN * 64 + (size_t)(k0 + 1) * 64 + (n & 63)];
        } else {
            if (k0 < FIN)     lo = root1[(size_t)k0 * 64 + (n - 192)];
            if (k0 + 1 < FIN) hi = root1[(size_t)(k0 + 1) * 64 + (n - 192)];
        }
        g_wt1[i] = f2bf2(lo, hi);
        return;
    }
    int j = i - 256 * 400;
    if (j < 8192) {                                      // wt2 [256][32]
        int n = j >> 5, s = j & 31;
        int jj = s & 7, k0 = (s >> 3) * 16 + (jj >> 1) * 2 + (jj & 1) * 8;
        float lo, hi;
        if (n < 192) {
            lo = W2[(n >> 6) * 4096 + k0 * 64 + (n & 63)];
            hi = W2[(n >> 6) * 4096 + (k0 + 1) * 64 + (n & 63)];
        } else {
            lo = root2[k0 * 64 + (n - 192)];
            hi = root2[(k0 + 1) * 64 + (n - 192)];
        }
        g_wt2[j] = f2bf2(lo, hi);
        return;
    }
    j -= 8192;
    if (j < 8192) {                                      // wt3
        int n = j >> 5, s = j & 31;
        int jj = s & 7, k0 = (s >> 3) * 16 + (jj >> 1) * 2 + (jj & 1) * 8;
        float lo, hi;
        if (n < 192) {
            lo = W3[(n >> 6) * 4096 + k0 * 64 + (n & 63)];
            hi = W3[(n >> 6) * 4096 + (k0 + 1) * 64 + (n & 63)];
        } else {
            lo = root3[k0 * 64 + (n - 192)];
            hi = root3[(k0 + 1) * 64 + (n - 192)];
        }
        g_wt3[j] = f2bf2(lo, hi);
        return;
    }
    j -= 8192;
    if (j < 4096) {                                      // wte [128][32]
        int n = j >> 5, s = j & 31;
        int jj = s & 7, k0 = (s >> 3) * 16 + (jj >> 1) * 2 + (jj & 1) * 8;
        float lo, hi;
        if (n < 64) { lo = ew1[k0 * 64 + n];               hi = ew1[(k0 + 1) * 64 + n]; }
        else        { lo = ew1[(64 + k0) * 64 + (n - 64)]; hi = ew1[(64 + k0 + 1) * 64 + (n - 64)]; }
        g_wte[j] = f2bf2(lo, hi);
    }
}

// ---------------- launch 2: convert + degree count ------------------------------
__global__ void k_convert(const void* __restrict__ ei, const void* __restrict__ et) {
    int i = blockIdx.x * blockDim.x + threadIdx.x;
    if (i >= EE) return;
    int r, c, t;
    if (g_is64) {
        const long long* p = (const long long*)ei;
        r = (int)p[i];
        c = (int)p[EE + i];
        t = (int)((const long long*)et)[i];
    } else {
        const int* p = (const int*)ei;
        r = p[i];
        c = p[EE + i];
        t = ((const int*)et)[i];
    }
    g_sd[i] = (uint32_t)r | ((uint32_t)c << 16);
    g_et8[i] = (uint8_t)t;
    atomicAdd(&g_cnt[t * NN + c], 1);
}

// ---------------- launch 3: offsets via block scan + global atomic base ---------
__global__ void k_off() {
    __shared__ int sh[256];
    __shared__ int s_base;
    int tid = threadIdx.x;
    int i = blockIdx.x * 256 + tid;
    int v = (i < SEG) ? g_cnt[i] : 0;
    sh[tid] = v;
    __syncthreads();
    for (int o = 1; o < 256; o <<= 1) {
        int t = (tid >= o) ? sh[tid - o] : 0;
        __syncthreads();
        sh[tid] += t;
        __syncthreads();
    }
    if (tid == 255) s_base = atomicAdd(&g_gctr, sh[255]);
    __syncthreads();
    if (i < SEG) {
        g_off[i] = sh[tid] - v + s_base;
        g_invc[i] = 1.0f / (float)(v > 0 ? v : 1);
    }
}
__global__ void k_scatter() {
    int e = blockIdx.x * blockDim.x + threadIdx.x;
    if (e >= EE) return;
    uint32_t sd = g_sd[e];
    int idx = (int)g_et8[e] * NN + (int)(sd >> 16);
    int pos = g_off[idx] + atomicAdd(&g_fill[idx], 1);
    g_sdl[pos] = sd;
    g_eidl[pos] = e;
}

// ---------------- GEMM: A (fp32 or bf16x2) @ bf16[N,Kp2]^T, N = NT*64 -----------
// 512 threads / 16 warps; MT = NT/2 row-tiles of 16 per warp; 4-stage cp.async.
// ABF=0: A fp32, smem rows 160B stride, plain cp8 loads (verified path).
// ABF=1: A bf16x2, smem rows 80B, ldmatrix.
template<int NT, int ABF>
__device__ __forceinline__ void issue_chunk(const void* __restrict__ X,
                                            const uint32_t* __restrict__ Wt,
                                            int M, int K, int Kp2, int m0, int c, int buf,
                                            uint32_t sb) {
    int tid = threadIdx.x;
    uint32_t bb = sb + (ABF ? 40960u : 81920u) + (uint32_t)buf * (uint32_t)(NT * 6144);
    if (ABF) {
        uint32_t ab = sb + (uint32_t)buf * 10240u;
        int row = tid >> 2, j = tid & 3;          // 512 units: 128 rows x 4 of 16B
        int ok = (m0 + row) < M;
        const uint32_t* src = (const uint32_t*)X + (size_t)(m0 + row) * Kp2 + c * 16 + j * 4;
        cp16(ab + row * 80 + j * 16, ok ? (const void*)src : X, ok ? 16 : 0);
    } else {
        uint32_t ab = sb + (uint32_t)buf * 20480u;
        int k0 = c * 32;
#pragma unroll
        for (int i = 0; i < 4; i++) {
            int u = i * 512 + tid;                // 2048 units: 128 rows x 16 of 8B
            int row = u >> 4, j = u & 15;
            int kk = k0 + j * 2;
            int ok = ((m0 + row) < M) && (kk < K);
            const float* src = ok ? ((const float*)X + (size_t)(m0 + row) * K + kk)
                                  : (const float*)X;
            int sz = ok ? ((K - kk >= 2) ? 8 : 4) : 0;
            cp8(ab + row * 160 + j * 8, src, sz);
        }
    }
#pragma unroll
    for (int i = 0; i < NT / 2; i++) {
        int u = i * 512 + tid;                    // NT*64 rows x 4 units of 16B
        int r2 = u >> 2, j2 = u & 3;
        cp16(bb + r2 * 96 + j2 * 16, Wt + (size_t)r2 * Kp2 + c * 16 + j2 * 4, 16);
    }
    asm volatile("cp.async.commit_group;" ::: "memory");
}

template<int NT, int ABF>
__global__ __launch_bounds__(512, 1) void k_mma(
    const void* __restrict__ X, const uint32_t* __restrict__ Wt,
    int M, int K, int Kp2,
    uint32_t* __restrict__ ob0, uint32_t* __restrict__ ob1,
    uint32_t* __restrict__ ob2, float* __restrict__ o3fp,
    const float* __restrict__ bias3)
{
    extern __shared__ float smf[];
    const uint32_t* smu = (const uint32_t*)smf;
    uint32_t sb = smem_u32(smf);
    const int MT = NT / 2;
    int tid = threadIdx.x, wid = tid >> 5, lane = tid & 31;
    int g = lane >> 2, tig = lane & 3;
    int wn = wid % NT, wm = wid / NT;
    int rowbase = wm * MT * 16;
    int m0 = blockIdx.x * 128;
    int NC = (K + 31) / 32;

    float acc[MT][8][4];
#pragma unroll
    for (int mt = 0; mt < MT; mt++)
#pragma unroll
        for (int nt = 0; nt < 8; nt++)
#pragma unroll
            for (int q = 0; q < 4; q++) acc[mt][nt][q] = 0.f;

    issue_chunk<NT, ABF>(X, Wt, M, K, Kp2, m0, 0, 0, sb);
    if (NC > 1) issue_chunk<NT, ABF>(X, Wt, M, K, Kp2, m0, 1, 1, sb);
    if (NC > 2) issue_chunk<NT, ABF>(X, Wt, M, K, Kp2, m0, 2, 2, sb);

    for (int c = 0; c < NC; c++) {
        int buf = c & 3;
        if (c + 3 < NC) {
            issue_chunk<NT, ABF>(X, Wt, M, K, Kp2, m0, c + 3, (c + 3) & 3, sb);
            asm volatile("cp.async.wait_group 3;" ::: "memory");
        } else if (c + 2 < NC) {
            asm volatile("cp.async.wait_group 2;" ::: "memory");
        } else if (c + 1 < NC) {
            asm volatile("cp.async.wait_group 1;" ::: "memory");
        } else {
            asm volatile("cp.async.wait_group 0;" ::: "memory");
        }
        __syncthreads();

        int bf = (ABF ? 10240 : 20480) + buf * (NT * 1536);   // u32 index
#pragma unroll
        for (int st = 0; st < 2; st++) {
            uint32_t A[MT][4];
#pragma unroll
            for (int mt = 0; mt < MT; mt++) {
                if (ABF) {
                    uint32_t addr = sb + (uint32_t)buf * 10240u
                        + (uint32_t)((rowbase + mt * 16 + (lane & 15)) * 80
                                     + (lane >> 4) * 16 + st * 32);
                    asm volatile(
                        "ldmatrix.sync.aligned.m8n8.x4.shared.b16 {%0,%1,%2,%3}, [%4];"
                        : "=r"(A[mt][0]), "=r"(A[mt][1]), "=r"(A[mt][2]), "=r"(A[mt][3])
                        : "r"(addr));
                } else {
                    int af = buf * 5120;                     // u32 per stage
                    int base = af + (rowbase + mt * 16 + g) * 40 + st * 16 + 2 * tig;
                    float2 x0 = *(const float2*)&smf[base];
                    float2 x1 = *(const float2*)&smf[base + 8 * 40];
                    float2 x2 = *(const float2*)&smf[base + 8];
                    float2 x3 = *(const float2*)&smf[base + 8 * 40 + 8];
                    A[mt][0] = f2bf2(x0.x, x0.y);
                    A[mt][1] = f2bf2(x1.x, x1.y);
                    A[mt][2] = f2bf2(x2.x, x2.y);
                    A[mt][3] = f2bf2(x3.x, x3.y);
                }
            }
#pragma unroll
            for (int nt = 0; nt < 8; nt++) {
                int nb = bf + (wn * 64 + nt * 8 + g) * 24 + st * 8 + tig * 2;
                uint2 bv = *(const uint2*)&smu[nb];
#pragma unroll
                for (int mt = 0; mt < MT; mt++)
                    mma16(acc[mt][nt], A[mt], bv.x, bv.y);
            }
        }
        __syncthreads();
    }

    bool fp = (wn == NT - 1) && (o3fp != nullptr);
    uint32_t* ob = (wn == 0) ? ob0 : ((wn == 1) ? ob1 : ob2);
#pragma unroll
    for (int mt = 0; mt < MT; mt++) {
        int mA = m0 + rowbase + mt * 16 + g;
        int mB = mA + 8;
#pragma unroll
        for (int nt = 0; nt < 8; nt++) {
            int col = nt * 8 + tig * 2;
            float c0 = acc[mt][nt][0], c1 = acc[mt][nt][1];
            float c2 = acc[mt][nt][2], c3 = acc[mt][nt][3];
            if (fp) {
                float bb0 = bias3[col], bb1 = bias3[col + 1];
                c0 += bb0; c1 += bb1; c2 += bb0; c3 += bb1;
                if (mA < M) *(float2*)(o3fp + (size_t)mA * 64 + col) = make_float2(c0, c1);
                if (mB < M) *(float2*)(o3fp + (size_t)mB * 64 + col) = make_float2(c2, c3);
            } else {
                if (mA < M) ob[(size_t)mA * 32 + (col >> 1)] = f2bf2(c0, c1);
                if (mB < M) ob[(size_t)mB * 32 + (col >> 1)] = f2bf2(c2, c3);
            }
        }
    }
}

// ---------------- CSR aggregation core: bf16 gathers (feat 2l, 2l+1) ------------
__device__ __forceinline__ void agg_core(const uint32_t* __restrict__ xr, int w, int lane,
                                         float& a0, float& a1) {
#pragma unroll
    for (int r = 0; r < RR; r++) {
        int idx = r * NN + w;
        int beg = g_off[idx], n = g_cnt[idx];
        const uint32_t* xrr = xr + (size_t)r * NN * 32;
        float s0 = 0.f, s1 = 0.f;
        for (int b = 0; b < n; b += 32) {
            int src = (b + lane < n) ? (int)(g_sdl[beg + b + lane] & 0xFFFFu) : 0;
            int m = min(32, n - b);
            int j = 0;
            for (; j + 8 <= m; j += 8) {
                uint32_t v[8];
#pragma unroll
                for (int q = 0; q < 8; q++)
                    v[q] = xrr[(size_t)__shfl_sync(~0u, src, j + q) * 32 + lane];
                float t0 = 0.f, t1 = 0.f;
#pragma unroll
                for (int q = 0; q < 8; q++) {
                    t0 += bflo(v[q]);
                    t1 += bfhi(v[q]);
                }
                s0 += t0; s1 += t1;
            }
            for (; j + 4 <= m; j += 4) {
                uint32_t v[4];
#pragma unroll
                for (int q = 0; q < 4; q++)
                    v[q] = xrr[(size_t)__shfl_sync(~0u, src, j + q) * 32 + lane];
#pragma unroll
                for (int q = 0; q < 4; q++) {
                    s0 += bflo(v[q]);
                    s1 += bfhi(v[q]);
                }
            }
            for (; j < m; j++) {
                uint32_t v = xrr[(size_t)__shfl_sync(~0u, src, j) * 32 + lane];
                s0 += bflo(v);
                s1 += bfhi(v);
            }
        }
        float ic = g_invc[idx];
        a0 += s0 * ic;
        a1 += s1 * ic;
    }
}

// agg + relu -> bf16x2 activation buffer
__global__ void k_agg(const uint32_t* __restrict__ xr, const float* __restrict__ io,
                      uint32_t* __restrict__ outb) {
    int w = (blockIdx.x * blockDim.x + threadIdx.x) >> 5;
    int lane = threadIdx.x & 31;
    if (w >= NN) return;
    float a0 = 0.f, a1 = 0.f;
    agg_core(xr, w, lane, a0, a1);
    float2 cur = *(const float2*)&io[(size_t)w * 64 + 2 * lane];
    float v0 = fmaxf(cur.x + a0, 0.f);
    float v1 = fmaxf(cur.y + a1, 0.f);
    outb[(size_t)w * 32 + lane] = f2bf2(v0, v1);
}

// ---------------- fused: agg(layer3) + LayerNorm + node head --------------------
__global__ void k_agg_ln_node(const uint32_t* __restrict__ xr, const float* __restrict__ io,
                              uint32_t* __restrict__ x3out,
                              const float* __restrict__ gg, const float* __restrict__ bb,
                              const float* __restrict__ nw1, const float* __restrict__ nb1,
                              const float* __restrict__ nw2, const float* __restrict__ nb2,
                              float* __restrict__ outp) {
    __shared__ float s_w1[64 * 32];
    __shared__ float s_b1[32], s_w2[64], s_b2[2], s_g[64], s_bb[64];
    int tid = threadIdx.x;
    for (int i = tid; i < 2048; i += blockDim.x) s_w1[i] = nw1[i];
    if (tid < 32) s_b1[tid] = nb1[tid];
    if (tid < 64) { s_w2[tid] = nw2[tid]; s_g[tid] = gg[tid]; s_bb[tid] = bb[tid]; }
    if (tid < 2)  s_b2[tid] = nb2[tid];
    __syncthreads();

    int w = (blockIdx.x * blockDim.x + tid) >> 5;
    int lane = tid & 31;
    if (w >= NN) return;
    float a0 = 0.f, a1 = 0.f;
    agg_core(xr, w, lane, a0, a1);
    float2 cur = *(const float2*)&io[(size_t)w * 64 + 2 * lane];
    float v0 = cur.x + a0;
    float v1 = cur.y + a1;

    float s = v0 + v1;
#pragma unroll
    for (int off = 16; off; off >>= 1) s += __shfl_xor_sync(~0u, s, off);
    float mu = s * (1.f / 64.f);
    float d0 = v0 - mu, d1 = v1 - mu;
    float q = d0 * d0 + d1 * d1;
#pragma unroll
    for (int off = 16; off; off >>= 1) q += __shfl_xor_sync(~0u, q, off);
    float rs = rsqrtf(q * (1.f / 64.f) + 1e-5f);
    float xa = d0 * rs * s_g[2 * lane]     + s_bb[2 * lane];
    float xb = d1 * rs * s_g[2 * lane + 1] + s_bb[2 * lane + 1];
    x3out[(size_t)w * 32 + lane] = f2bf2(xa, xb);

    float acc = s_b1[lane];
#pragma unroll
    for (int k = 0; k < 32; k++) {
        float x0 = __shfl_sync(~0u, xa, k);
        float x1 = __shfl_sync(~0u, xb, k);
        acc += x0 * s_w1[(2 * k) * 32 + lane] + x1 * s_w1[(2 * k + 1) * 32 + lane];
    }
    float nh = fmaxf(acc, 0.f);
    float p0 = nh * s_w2[lane * 2 + 0];
    float p1 = nh * s_w2[lane * 2 + 1];
#pragma unroll
    for (int off = 16; off; off >>= 1) {
        p0 += __shfl_xor_sync(~0u, p0, off);
        p1 += __shfl_xor_sync(~0u, p1, off);
    }
    if (lane == 0) {
        float l0 = p0 + s_b2[0], l1 = p1 + s_b2[1];
        float mx = fmaxf(l0, l1);
        float lse = __logf(__expf(l0 - mx) + __expf(l1 - mx)) + mx;
        outp[(size_t)3 * EE + (size_t)w * 2 + 0] = l0 - lse;
        outp[(size_t)3 * EE + (size_t)w * 2 + 1] = l1 - lse;
    }
}

// ---------------- edge classifier, CSR order, 8 lanes/edge, uint4 gathers -------
__global__ void k_edge(const uint4* __restrict__ ea4, const uint4* __restrict__ eb4,
                       const float* __restrict__ eb1, const float* __restrict__ ew2,
                       const float* __restrict__ eb2, float* __restrict__ outp) {
    __shared__ float s_b1[64], s_w2[192], s_b2[3];
    int tid = threadIdx.x;
    if (tid < 64)  s_b1[tid] = eb1[tid];
    if (tid < 192) s_w2[tid] = ew2[tid];
    if (tid < 3)   s_b2[tid] = eb2[tid];
    __syncthreads();

    int gid = blockIdx.x * blockDim.x + tid;
    int p = gid >> 3, sub = tid & 7;
    if (p >= EE) return;
    uint32_t sd = g_sdl[p];
    int r  = (int)(sd & 0xFFFFu);
    int c  = (int)(sd >> 16);
    int id = g_eidl[p];
    uint4 va = ea4[(size_t)r * 8 + sub];     // feats 8sub..8sub+7
    uint4 vb = eb4[(size_t)c * 8 + sub];
    float h[8];
    h[0] = fmaxf(bflo(va.x) + bflo(vb.x) + s_b1[sub * 8 + 0], 0.f);
    h[1] = fmaxf(bfhi(va.x) + bfhi(vb.x) + s_b1[sub * 8 + 1], 0.f);
    h[2] = fmaxf(bflo(va.y) + bflo(vb.y) + s_b1[sub * 8 + 2], 0.f);
    h[3] = fmaxf(bfhi(va.y) + bfhi(vb.y) + s_b1[sub * 8 + 3], 0.f);
    h[4] = fmaxf(bflo(va.z) + bflo(vb.z) + s_b1[sub * 8 + 4], 0.f);
    h[5] = fmaxf(bfhi(va.z) + bfhi(vb.z) + s_b1[sub * 8 + 5], 0.f);
    h[6] = fmaxf(bflo(va.w) + bflo(vb.w) + s_b1[sub * 8 + 6], 0.f);
    h[7] = fmaxf(bfhi(va.w) + bfhi(vb.w) + s_b1[sub * 8 + 7], 0.f);
    float p0 = 0.f, p1 = 0.f, p2 = 0.f;
#pragma unroll
    for (int i = 0; i < 8; i++) {
        int f = sub * 8 + i;
        p0 += h[i] * s_w2[f * 3 + 0];
        p1 += h[i] * s_w2[f * 3 + 1];
        p2 += h[i] * s_w2[f * 3 + 2];
    }
#pragma unroll
    for (int off = 4; off; off >>= 1) {
        p0 += __shfl_xor_sync(~0u, p0, off);
        p1 += __shfl_xor_sync(~0u, p1, off);
        p2 += __shfl_xor_sync(~0u, p2, off);
    }
    if (sub == 0) {
        float l0 = p0 + s_b2[0], l1 = p1 + s_b2[1], l2 = p2 + s_b2[2];
        float mx = fmaxf(l0, fmaxf(l1, l2));
        float lse = __logf(__expf(l0 - mx) + __expf(l1 - mx) + __expf(l2 - mx)) + mx;
        outp[(size_t)id * 3 + 0] = l0 - lse;
        outp[(size_t)id * 3 + 1] = l1 - lse;
        outp[(size_t)id * 3 + 2] = l2 - lse;
    }
}

// ---------------- host orchestration -------------------------------------------
extern "C" void kernel_launch(void* const* d_in, const int* in_sizes, int n_in,
                              void* d_out, int out_size) {
    const float* x     = (const float*)d_in[0];
    const void*  eidx  = d_in[1];
    const void*  etyp  = d_in[2];
    const float* W1    = (const float*)d_in[3];
    const float* root1 = (const float*)d_in[4];
    const float* b1    = (const float*)d_in[5];
    const float* W2    = (const float*)d_in[6];
    const float* root2 = (const float*)d_in[7];
    const float* b2    = (const float*)d_in[8];
    const float* W3    = (const float*)d_in[9];
    const float* root3 = (const float*)d_in[10];
    const float* b3    = (const float*)d_in[11];
    const float* ln_g  = (const float*)d_in[12];
    const float* ln_b  = (const float*)d_in[13];
    const float* ew1   = (const float*)d_in[14];
    const float* eb1   = (const float*)d_in[15];
    const float* ew2   = (const float*)d_in[16];
    const float* eb2   = (const float*)d_in[17];
    const float* nw1   = (const float*)d_in[18];
    const float* nb1   = (const float*)d_in[19];
    const float* nw2   = (const float*)d_in[20];
    const float* nb2   = (const float*)d_in[21];
    float* out = (float*)d_out;

    float *p_bufa, *p_bufb;
    uint32_t *p_xr, *p_hb, *p_ea, *p_eb, *p_wt1, *p_wt2, *p_wt3, *p_wte;
    cudaGetSymbolAddress((void**)&p_xr,   g_xr);
    cudaGetSymbolAddress((void**)&p_bufa, g_bufa);
    cudaGetSymbolAddress((void**)&p_bufb, g_bufb);
    cudaGetSymbolAddress((void**)&p_hb,   g_hb);
    cudaGetSymbolAddress((void**)&p_ea,   g_ea);
    cudaGetSymbolAddress((void**)&p_eb,   g_eb);
    cudaGetSymbolAddress((void**)&p_wt1,  g_wt1);
    cudaGetSymbolAddress((void**)&p_wt2,  g_wt2);
    cudaGetSymbolAddress((void**)&p_wt3,  g_wt3);
    cudaGetSymbolAddress((void**)&p_wte,  g_wte);

    const int SMEM_F4 = 81920 + 4 * 4 * 6144;   // 180224 B (fp32-A, NT=4)
    const int SMEM_B4 = 40960 + 4 * 4 * 6144;   // 139264 B (bf16-A, NT=4)
    const int SMEM_B2 = 40960 + 4 * 2 * 6144;   //  90112 B (bf16-A, NT=2)
    cudaFuncSetAttribute((const void*)k_mma<4, 0>, cudaFuncAttributeMaxDynamicSharedMemorySize, SMEM_F4);
    cudaFuncSetAttribute((const void*)k_mma<4, 1>, cudaFuncAttributeMaxDynamicSharedMemorySize, SMEM_B4);
    cudaFuncSetAttribute((const void*)k_mma<2, 1>, cudaFuncAttributeMaxDynamicSharedMemorySize, SMEM_B2);

    int tiles = (NN + 127) / 128;            // 391
    int warpNBlocks = (NN * 32 + 255) / 256;
    int packN = 256 * 400 + 8192 + 8192 + 4096;
    int initB = SCANB + (packN + 255) / 256;
    size_t NH32 = (size_t)NN * 32;

    // 1-4: init, convert+count, offsets, layer-1 GEMM (profiled slot 4)
    k_init<<<initB, 256>>>((const unsigned int*)eidx, W1, root1, W2, root2, W3, root3, ew1);
    k_convert<<<(EE + 255) / 256, 256>>>(eidx, etyp);
    k_off<<<SCANB, 256>>>();
    k_mma<4, 0><<<tiles, 512, SMEM_F4>>>(x, p_wt1, NN, FIN, 400,
                                         p_xr, p_xr + NH32, p_xr + 2 * NH32, p_bufa, b1);

    // 5: scatter into CSR order
    k_scatter<<<(EE + 255) / 256, 256>>>();

    // 6: layer-1 aggregate + relu -> bf16 h1
    k_agg<<<warpNBlocks, 256>>>(p_xr, p_bufa, p_hb);

    // 7-8: layer 2 (A = bf16 h1)
    k_mma<4, 1><<<tiles, 512, SMEM_B4>>>(p_hb, p_wt2, NN, 64, 32,
                                         p_xr, p_xr + NH32, p_xr + 2 * NH32, p_bufb, b2);
    k_agg<<<warpNBlocks, 256>>>(p_xr, p_bufb, p_hb);

    // 9-10: layer 3 + fused agg/LN/node-head (x3 bf16 -> g_hb)
    k_mma<4, 1><<<tiles, 512, SMEM_B4>>>(p_hb, p_wt3, NN, 64, 32,
                                         p_xr, p_xr + NH32, p_xr + 2 * NH32, p_bufa, b3);
    k_agg_ln_node<<<warpNBlocks, 256>>>(p_xr, p_bufa, p_hb, ln_g, ln_b,
                                        nw1, nb1, nw2, nb2, out);

    // 11-12: edge head (A = x3 bf16)
    k_mma<2, 1><<<tiles, 512, SMEM_B2>>>(p_hb, p_wte, NN, 64, 32,
                                         p_ea, p_eb, nullptr, nullptr, nullptr);
    k_edge<<<(EE * 8 + 255) / 256, 256>>>((const uint4*)p_ea, (const uint4*)p_eb,
                                          eb1, ew2, eb2, out);
}

// round 15
// speedup vs baseline: 1.1841x; 1.0227x over previous
#include <cuda_runtime.h>
#include <math.h>
#include <stdint.h>

#define NN 50000
#define EE 1600000
#define FIN 770
#define RR 3
#define SEG (RR * NN)               // 150000
#define SCANB ((SEG + 255) / 256)   // 586
#define CONVB 1024

// ---------------- scratch ------------------------------------------------------
__device__ uint32_t g_xr[(size_t)RR * NN * 32];   // bf16x2 rows (64 feat = 32 u32)
__device__ float    g_bufa[(size_t)NN * 64];      // fp32 root results
__device__ float    g_bufb[(size_t)NN * 64];
__device__ uint32_t g_hb[(size_t)NN * 32];        // bf16x2 activations (h1/h2/x3)
__device__ uint32_t g_ea[(size_t)NN * 32];
__device__ uint32_t g_eb[(size_t)NN * 32];
__device__ float g_invc[SEG];
__device__ int   g_cnt[SEG];
__device__ int   g_off[SEG];
__device__ int   g_fill[SEG];
__device__ int   g_gctr;
__device__ uint32_t g_sd[EE];       // src | dst<<16 (edge order)
__device__ uint8_t  g_et8[EE];
__device__ uint32_t g_sdl[EE];      // packed, CSR order
__device__ int      g_eidl[EE];
__device__ int   g_is64;
__device__ uint32_t g_wt1[256 * 400];   // bf16x2 pairs, [N][Kp2]
__device__ uint32_t g_wt2[256 * 32];
__device__ uint32_t g_wt3[256 * 32];
__device__ uint32_t g_wte[128 * 32];

// ---------------- helpers ------------------------------------------------------
__device__ __forceinline__ uint32_t smem_u32(const void* p) {
    uint32_t a;
    asm("{ .reg .u64 t; cvta.to.shared.u64 t, %1; cvt.u32.u64 %0, t; }" : "=r"(a) : "l"(p));
    return a;
}
__device__ __forceinline__ void cp16(uint32_t dst, const void* src, int sz) {
    asm volatile("cp.async.cg.shared.global [%0], [%1], 16, %2;"
                 :: "r"(dst), "l"(src), "r"(sz) : "memory");
}
__device__ __forceinline__ void cp8(uint32_t dst, const void* src, int sz) {
    asm volatile("cp.async.ca.shared.global [%0], [%1], 8, %2;"
                 :: "r"(dst), "l"(src), "r"(sz) : "memory");
}
__device__ __forceinline__ uint32_t f2bf2(float lo, float hi) {
    uint32_t r;
    asm("cvt.rn.bf16x2.f32 %0, %1, %2;" : "=r"(r) : "f"(hi), "f"(lo));
    return r;
}
__device__ __forceinline__ float bflo(uint32_t v) { return __uint_as_float(v << 16); }
__device__ __forceinline__ float bfhi(uint32_t v) { return __uint_as_float(v & 0xFFFF0000u); }
__device__ __forceinline__ void mma16(float* c, const uint32_t* a, uint32_t b0, uint32_t b1) {
    asm volatile(
        "mma.sync.aligned.m16n8k16.row.col.f32.bf16.bf16.f32 "
        "{%0,%1,%2,%3}, {%4,%5,%6,%7}, {%8,%9}, {%0,%1,%2,%3};"
        : "+f"(c[0]), "+f"(c[1]), "+f"(c[2]), "+f"(c[3])
        : "r"(a[0]), "r"(a[1]), "r"(a[2]), "r"(a[3]), "r"(b0), "r"(b1));
}

// ---------------- launch 1: fused detect+zero + weight pack ---------------------
__global__ void k_init(const unsigned int* __restrict__ ei,
                       const float* __restrict__ W1, const float* __restrict__ root1,
                       const float* __restrict__ W2, const float* __restrict__ root2,
                       const float* __restrict__ W3, const float* __restrict__ root3,
                       const float* __restrict__ ew1) {
    int b = blockIdx.x;
    if (b < SCANB) {
        int i = b * 256 + threadIdx.x;
        if (i < SEG) { g_cnt[i] = 0; g_fill[i] = 0; }
        if (i == 0) {
            g_gctr = 0;
            int is64 = 1;
            for (int j = 0; j < 64; j++)
                if (ei[2 * j + 1] != 0u) { is64 = 0; break; }
            g_is64 = is64;
        }
        return;
    }
    int i = (b - SCANB) * 256 + threadIdx.x;
    if (i < 256 * 400) {                                 // wt1  [256][400]
        int n = i / 400, s = i % 400;
        int jj = s & 7, k0 = (s >> 3) * 16 + (jj >> 1) * 2 + (jj & 1) * 8;
        float lo = 0.f, hi = 0.f;
        if (n < 192) {
            if (k0 < FIN)     lo = W1[(size_t)(n >> 6) * FIN * 64 + (size_t)k0 * 64 + (n & 63)];
            if (k0 + 1 < FIN) hi = W1[(size_t)(n >> 6) * FIN * 64 + (size_t)(k0 + 1) * 64 + (n & 63)];
        } else {
            if (k0 < FIN)     lo = root1[(size_t)k0 * 64 + (n - 192)];
            if (k0 + 1 < FIN) hi = root1[(size_t)(k0 + 1) * 64 + (n - 192)];
        }
        g_wt1[i] = f2bf2(lo, hi);
        return;
    }
    int j = i - 256 * 400;
    if (j < 8192) {                                      // wt2 [256][32]
        int n = j >> 5, s = j & 31;
        int jj = s & 7, k0 = (s >> 3) * 16 + (jj >> 1) * 2 + (jj & 1) * 8;
        float lo, hi;
        if (n < 192) {
            lo = W2[(n >> 6) * 4096 + k0 * 64 + (n & 63)];
            hi = W2[(n >> 6) * 4096 + (k0 + 1) * 64 + (n & 63)];
        } else {
            lo = root2[k0 * 64 + (n - 192)];
            hi = root2[(k0 + 1) * 64 + (n - 192)];
        }
        g_wt2[j] = f2bf2(lo, hi);
        return;
    }
    j -= 8192;
    if (j < 8192) {                                      // wt3
        int n = j >> 5, s = j & 31;
        int jj = s & 7, k0 = (s >> 3) * 16 + (jj >> 1) * 2 + (jj & 1) * 8;
        float lo, hi;
        if (n < 192) {
            lo = W3[(n >> 6) * 4096 + k0 * 64 + (n & 63)];
            hi = W3[(n >> 6) * 4096 + (k0 + 1) * 64 + (n & 63)];
        } else {
            lo = root3[k0 * 64 + (n - 192)];
            hi = root3[(k0 + 1) * 64 + (n - 192)];
        }
        g_wt3[j] = f2bf2(lo, hi);
        return;
    }
    j -= 8192;
    if (j < 4096) {                                      // wte [128][32]
        int n = j >> 5, s = j & 31;
        int jj = s & 7, k0 = (s >> 3) * 16 + (jj >> 1) * 2 + (jj & 1) * 8;
        float lo, hi;
        if (n < 64) { lo = ew1[k0 * 64 + n];               hi = ew1[(k0 + 1) * 64 + n]; }
        else        { lo = ew1[(64 + k0) * 64 + (n - 64)]; hi = ew1[(64 + k0 + 1) * 64 + (n - 64)]; }
        g_wte[j] = f2bf2(lo, hi);
    }
}

// ---------------- offsets via block scan + global atomic base -------------------
__global__ void k_off() {
    __shared__ int sh[256];
    __shared__ int s_base;
    int tid = threadIdx.x;
    int i = blockIdx.x * 256 + tid;
    int v = (i < SEG) ? g_cnt[i] : 0;
    sh[tid] = v;
    __syncthreads();
    for (int o = 1; o < 256; o <<= 1) {
        int t = (tid >= o) ? sh[tid - o] : 0;
        __syncthreads();
        sh[tid] += t;
        __syncthreads();
    }
    if (tid == 255) s_base = atomicAdd(&g_gctr, sh[255]);
    __syncthreads();
    if (i < SEG) {
        g_off[i] = sh[tid] - v + s_base;
        g_invc[i] = 1.0f / (float)(v > 0 ? v : 1);
    }
}
__global__ void k_scatter() {
    int e = blockIdx.x * blockDim.x + threadIdx.x;
    if (e >= EE) return;
    uint32_t sd = g_sd[e];
    int idx = (int)g_et8[e] * NN + (int)(sd >> 16);
    int pos = g_off[idx] + atomicAdd(&g_fill[idx], 1);
    g_sdl[pos] = sd;
    g_eidl[pos] = e;
}

// ---------------- GEMM: A (fp32 or bf16x2) @ bf16[N,Kp2]^T, N = NT*64 -----------
// 512 threads / 16 warps; MT = NT/2 row-tiles of 16 per warp; 3-stage cp.async.
// Blocks >= mtiles run edge convert+count (fused backfill; ei != nullptr).
template<int NT, int ABF>
__device__ __forceinline__ void issue_chunk(const void* __restrict__ X,
                                            const uint32_t* __restrict__ Wt,
                                            int M, int K, int Kp2, int m0, int c, int buf,
                                            uint32_t sb) {
    int tid = threadIdx.x;
    uint32_t bb = sb + (ABF ? 30720u : 61440u) + (uint32_t)buf * (uint32_t)(NT * 6144);
    if (ABF) {
        uint32_t ab = sb + (uint32_t)buf * 10240u;
        int row = tid >> 2, j = tid & 3;          // 512 units: 128 rows x 4 of 16B
        int ok = (m0 + row) < M;
        const uint32_t* src = (const uint32_t*)X + (size_t)(m0 + row) * Kp2 + c * 16 + j * 4;
        cp16(ab + row * 80 + j * 16, ok ? (const void*)src : X, ok ? 16 : 0);
    } else {
        uint32_t ab = sb + (uint32_t)buf * 20480u;
        int k0 = c * 32;
#pragma unroll
        for (int i = 0; i < 4; i++) {
            int u = i * 512 + tid;                // 2048 units: 128 rows x 16 of 8B
            int row = u >> 4, j = u & 15;
            int kk = k0 + j * 2;
            int ok = ((m0 + row) < M) && (kk < K);
            const float* src = ok ? ((const float*)X + (size_t)(m0 + row) * K + kk)
                                  : (const float*)X;
            int sz = ok ? ((K - kk >= 2) ? 8 : 4) : 0;
            cp8(ab + row * 160 + j * 8, src, sz);
        }
    }
#pragma unroll
    for (int i = 0; i < NT / 2; i++) {
        int u = i * 512 + tid;                    // NT*64 rows x 4 units of 16B
        int r2 = u >> 2, j2 = u & 3;
        cp16(bb + r2 * 96 + j2 * 16, Wt + (size_t)r2 * Kp2 + c * 16 + j2 * 4, 16);
    }
    asm volatile("cp.async.commit_group;" ::: "memory");
}

template<int NT, int ABF>
__global__ __launch_bounds__(512, 1) void k_mma(
    const void* __restrict__ X, const uint32_t* __restrict__ Wt,
    int M, int K, int Kp2,
    uint32_t* __restrict__ ob0, uint32_t* __restrict__ ob1,
    uint32_t* __restrict__ ob2, float* __restrict__ o3fp,
    const float* __restrict__ bias3,
    const void* __restrict__ ei, const void* __restrict__ et, int mtiles)
{
    if (blockIdx.x >= mtiles) {                   // fused edge convert + count
        int base = (blockIdx.x - mtiles) * 512 + threadIdx.x;
        int stride = (gridDim.x - mtiles) * 512;
        if (g_is64) {
            const long long* p = (const long long*)ei;
            const long long* q = (const long long*)et;
            for (int i = base; i < EE; i += stride) {
                int r = (int)p[i], c = (int)p[EE + i], t = (int)q[i];
                g_sd[i] = (uint32_t)r | ((uint32_t)c << 16);
                g_et8[i] = (uint8_t)t;
                atomicAdd(&g_cnt[t * NN + c], 1);
            }
        } else {
            const int* p = (const int*)ei;
            const int* q = (const int*)et;
            for (int i = base; i < EE; i += stride) {
                int r = p[i], c = p[EE + i], t = q[i];
                g_sd[i] = (uint32_t)r | ((uint32_t)c << 16);
                g_et8[i] = (uint8_t)t;
                atomicAdd(&g_cnt[t * NN + c], 1);
            }
        }
        return;
    }

    extern __shared__ float smf[];
    const uint32_t* smu = (const uint32_t*)smf;
    uint32_t sb = smem_u32(smf);
    const int MT = NT / 2;
    int tid = threadIdx.x, wid = tid >> 5, lane = tid & 31;
    int g = lane >> 2, tig = lane & 3;
    int wn = wid % NT, wm = wid / NT;
    int rowbase = wm * MT * 16;
    int m0 = blockIdx.x * 128;
    int NC = (K + 31) / 32;

    float acc[MT][8][4];
#pragma unroll
    for (int mt = 0; mt < MT; mt++)
#pragma unroll
        for (int nt = 0; nt < 8; nt++)
#pragma unroll
            for (int q = 0; q < 4; q++) acc[mt][nt][q] = 0.f;

    issue_chunk<NT, ABF>(X, Wt, M, K, Kp2, m0, 0, 0, sb);
    if (NC > 1) issue_chunk<NT, ABF>(X, Wt, M, K, Kp2, m0, 1, 1, sb);

    int buf = 0;
    for (int c = 0; c < NC; c++) {
        if (c + 2 < NC) {
            int b2 = buf + 2; if (b2 >= 3) b2 -= 3;
            issue_chunk<NT, ABF>(X, Wt, M, K, Kp2, m0, c + 2, b2, sb);
            asm volatile("cp.async.wait_group 2;" ::: "memory");
        } else if (c + 1 < NC) {
            asm volatile("cp.async.wait_group 1;" ::: "memory");
        } else {
            asm volatile("cp.async.wait_group 0;" ::: "memory");
        }
        __syncthreads();

        int bf = (ABF ? 7680 : 15360) + buf * (NT * 1536);   // u32 index
#pragma unroll
        for (int st = 0; st < 2; st++) {
            uint32_t A[MT][4];
#pragma unroll
            for (int mt = 0; mt < MT; mt++) {
                if (ABF) {
                    uint32_t addr = sb + (uint32_t)buf * 10240u
                        + (uint32_t)((rowbase + mt * 16 + (lane & 15)) * 80
                                     + (lane >> 4) * 16 + st * 32);
                    asm volatile(
                        "ldmatrix.sync.aligned.m8n8.x4.shared.b16 {%0,%1,%2,%3}, [%4];"
                        : "=r"(A[mt][0]), "=r"(A[mt][1]), "=r"(A[mt][2]), "=r"(A[mt][3])
                        : "r"(addr));
                } else {
                    int af = buf * 5120;                     // u32 per stage
                    int base = af + (rowbase + mt * 16 + g) * 40 + st * 16 + 2 * tig;
                    float2 x0 = *(const float2*)&smf[base];
                    float2 x1 = *(const float2*)&smf[base + 8 * 40];
                    float2 x2 = *(const float2*)&smf[base + 8];
                    float2 x3 = *(const float2*)&smf[base + 8 * 40 + 8];
                    A[mt][0] = f2bf2(x0.x, x0.y);
                    A[mt][1] = f2bf2(x1.x, x1.y);
                    A[mt][2] = f2bf2(x2.x, x2.y);
                    A[mt][3] = f2bf2(x3.x, x3.y);
                }
            }
#pragma unroll
            for (int nt = 0; nt < 8; nt++) {
                int nb = bf + (wn * 64 + nt * 8 + g) * 24 + st * 8 + tig * 2;
                uint2 bv = *(const uint2*)&smu[nb];
#pragma unroll
                for (int mt = 0; mt < MT; mt++)
                    mma16(acc[mt][nt], A[mt], bv.x, bv.y);
            }
        }
        __syncthreads();
        buf = (buf + 1 == 3) ? 0 : buf + 1;
    }

    bool fp = (wn == NT - 1) && (o3fp != nullptr);
    uint32_t* ob = (wn == 0) ? ob0 : ((wn == 1) ? ob1 : ob2);
#pragma unroll
    for (int mt = 0; mt < MT; mt++) {
        int mA = m0 + rowbase + mt * 16 + g;
        int mB = mA + 8;
#pragma unroll
        for (int nt = 0; nt < 8; nt++) {
            int col = nt * 8 + tig * 2;
            float c0 = acc[mt][nt][0], c1 = acc[mt][nt][1];
            float c2 = acc[mt][nt][2], c3 = acc[mt][nt][3];
            if (fp) {
                float bb0 = bias3[col], bb1 = bias3[col + 1];
                c0 += bb0; c1 += bb1; c2 += bb0; c3 += bb1;
                if (mA < M) *(float2*)(o3fp + (size_t)mA * 64 + col) = make_float2(c0, c1);
                if (mB < M) *(float2*)(o3fp + (size_t)mB * 64 + col) = make_float2(c2, c3);
            } else {
                if (mA < M) ob[(size_t)mA * 32 + (col >> 1)] = f2bf2(c0, c1);
                if (mB < M) ob[(size_t)mB * 32 + (col >> 1)] = f2bf2(c2, c3);
            }
        }
    }
}

// ---------------- CSR aggregation core: bf16 gathers (feat 2l, 2l+1) ------------
__device__ __forceinline__ void agg_core(const uint32_t* __restrict__ xr, int w, int lane,
                                         float& a0, float& a1) {
#pragma unroll
    for (int r = 0; r < RR; r++) {
        int idx = r * NN + w;
        int beg = g_off[idx], n = g_cnt[idx];
        const uint32_t* xrr = xr + (size_t)r * NN * 32;
        float s0 = 0.f, s1 = 0.f;
        for (int b = 0; b < n; b += 32) {
            int src = (b + lane < n) ? (int)(g_sdl[beg + b + lane] & 0xFFFFu) : 0;
            int m = min(32, n - b);
            int j = 0;
            for (; j + 8 <= m; j += 8) {
                uint32_t v[8];
#pragma unroll
                for (int q = 0; q < 8; q++)
                    v[q] = xrr[(size_t)__shfl_sync(~0u, src, j + q) * 32 + lane];
                float t0 = 0.f, t1 = 0.f;
#pragma unroll
                for (int q = 0; q < 8; q++) {
                    t0 += bflo(v[q]);
                    t1 += bfhi(v[q]);
                }
                s0 += t0; s1 += t1;
            }
            for (; j + 4 <= m; j += 4) {
                uint32_t v[4];
#pragma unroll
                for (int q = 0; q < 4; q++)
                    v[q] = xrr[(size_t)__shfl_sync(~0u, src, j + q) * 32 + lane];
#pragma unroll
                for (int q = 0; q < 4; q++) {
                    s0 += bflo(v[q]);
                    s1 += bfhi(v[q]);
                }
            }
            for (; j < m; j++) {
                uint32_t v = xrr[(size_t)__shfl_sync(~0u, src, j) * 32 + lane];
                s0 += bflo(v);
                s1 += bfhi(v);
            }
        }
        float ic = g_invc[idx];
        a0 += s0 * ic;
        a1 += s1 * ic;
    }
}

// agg + relu -> bf16x2 activation buffer
__global__ void k_agg(const uint32_t* __restrict__ xr, const float* __restrict__ io,
                      uint32_t* __restrict__ outb) {
    int w = (blockIdx.x * blockDim.x + threadIdx.x) >> 5;
    int lane = threadIdx.x & 31;
    if (w >= NN) return;
    float a0 = 0.f, a1 = 0.f;
    agg_core(xr, w, lane, a0, a1);
    float2 cur = *(const float2*)&io[(size_t)w * 64 + 2 * lane];
    float v0 = fmaxf(cur.x + a0, 0.f);
    float v1 = fmaxf(cur.y + a1, 0.f);
    outb[(size_t)w * 32 + lane] = f2bf2(v0, v1);
}

// ---------------- fused: agg(layer3) + LayerNorm + node head --------------------
__global__ void k_agg_ln_node(const uint32_t* __restrict__ xr, const float* __restrict__ io,
                              uint32_t* __restrict__ x3out,
                              const float* __restrict__ gg, const float* __restrict__ bb,
                              const float* __restrict__ nw1, const float* __restrict__ nb1,
                              const float* __restrict__ nw2, const float* __restrict__ nb2,
                              float* __restrict__ outp) {
    __shared__ float s_w1[64 * 32];
    __shared__ float s_b1[32], s_w2[64], s_b2[2], s_g[64], s_bb[64];
    int tid = threadIdx.x;
    for (int i = tid; i < 2048; i += blockDim.x) s_w1[i] = nw1[i];
    if (tid < 32) s_b1[tid] = nb1[tid];
    if (tid < 64) { s_w2[tid] = nw2[tid]; s_g[tid] = gg[tid]; s_bb[tid] = bb[tid]; }
    if (tid < 2)  s_b2[tid] = nb2[tid];
    __syncthreads();

    int w = (blockIdx.x * blockDim.x + tid) >> 5;
    int lane = tid & 31;
    if (w >= NN) return;
    float a0 = 0.f, a1 = 0.f;
    agg_core(xr, w, lane, a0, a1);
    float2 cur = *(const float2*)&io[(size_t)w * 64 + 2 * lane];
    float v0 = cur.x + a0;
    float v1 = cur.y + a1;

    float s = v0 + v1;
#pragma unroll
    for (int off = 16; off; off >>= 1) s += __shfl_xor_sync(~0u, s, off);
    float mu = s * (1.f / 64.f);
    float d0 = v0 - mu, d1 = v1 - mu;
    float q = d0 * d0 + d1 * d1;
#pragma unroll
    for (int off = 16; off; off >>= 1) q += __shfl_xor_sync(~0u, q, off);
    float rs = rsqrtf(q * (1.f / 64.f) + 1e-5f);
    float xa = d0 * rs * s_g[2 * lane]     + s_bb[2 * lane];
    float xb = d1 * rs * s_g[2 * lane + 1] + s_bb[2 * lane + 1];
    x3out[(size_t)w * 32 + lane] = f2bf2(xa, xb);

    float acc = s_b1[lane];
#pragma unroll
    for (int k = 0; k < 32; k++) {
        float x0 = __shfl_sync(~0u, xa, k);
        float x1 = __shfl_sync(~0u, xb, k);
        acc += x0 * s_w1[(2 * k) * 32 + lane] + x1 * s_w1[(2 * k + 1) * 32 + lane];
    }
    float nh = fmaxf(acc, 0.f);
    float p0 = nh * s_w2[lane * 2 + 0];
    float p1 = nh * s_w2[lane * 2 + 1];
#pragma unroll
    for (int off = 16; off; off >>= 1) {
        p0 += __shfl_xor_sync(~0u, p0, off);
        p1 += __shfl_xor_sync(~0u, p1, off);
    }
    if (lane == 0) {
        float l0 = p0 + s_b2[0], l1 = p1 + s_b2[1];
        float mx = fmaxf(l0, l1);
        float lse = __logf(__expf(l0 - mx) + __expf(l1 - mx)) + mx;
        outp[(size_t)3 * EE + (size_t)w * 2 + 0] = l0 - lse;
        outp[(size_t)3 * EE + (size_t)w * 2 + 1] = l1 - lse;
    }
}

// ---------------- edge classifier, CSR order, 8 lanes/edge, uint4 gathers -------
__global__ void k_edge(const uint4* __restrict__ ea4, const uint4* __restrict__ eb4,
                       const float* __restrict__ eb1, const float* __restrict__ ew2,
                       const float* __restrict__ eb2, float* __restrict__ outp) {
    __shared__ float s_b1[64], s_w2[192], s_b2[3];
    int tid = threadIdx.x;
    if (tid < 64)  s_b1[tid] = eb1[tid];
    if (tid < 192) s_w2[tid] = ew2[tid];
    if (tid < 3)   s_b2[tid] = eb2[tid];
    __syncthreads();

    int gid = blockIdx.x * blockDim.x + tid;
    int p = gid >> 3, sub = tid & 7;
    if (p >= EE) return;
    uint32_t sd = g_sdl[p];
    int r  = (int)(sd & 0xFFFFu);
    int c  = (int)(sd >> 16);
    int id = g_eidl[p];
    uint4 va = ea4[(size_t)r * 8 + sub];     // feats 8sub..8sub+7
    uint4 vb = eb4[(size_t)c * 8 + sub];
    float h[8];
    h[0] = fmaxf(bflo(va.x) + bflo(vb.x) + s_b1[sub * 8 + 0], 0.f);
    h[1] = fmaxf(bfhi(va.x) + bfhi(vb.x) + s_b1[sub * 8 + 1], 0.f);
    h[2] = fmaxf(bflo(va.y) + bflo(vb.y) + s_b1[sub * 8 + 2], 0.f);
    h[3] = fmaxf(bfhi(va.y) + bfhi(vb.y) + s_b1[sub * 8 + 3], 0.f);
    h[4] = fmaxf(bflo(va.z) + bflo(vb.z) + s_b1[sub * 8 + 4], 0.f);
    h[5] = fmaxf(bfhi(va.z) + bfhi(vb.z) + s_b1[sub * 8 + 5], 0.f);
    h[6] = fmaxf(bflo(va.w) + bflo(vb.w) + s_b1[sub * 8 + 6], 0.f);
    h[7] = fmaxf(bfhi(va.w) + bfhi(vb.w) + s_b1[sub * 8 + 7], 0.f);
    float p0 = 0.f, p1 = 0.f, p2 = 0.f;
#pragma unroll
    for (int i = 0; i < 8; i++) {
        int f = sub * 8 + i;
        p0 += h[i] * s_w2[f * 3 + 0];
        p1 += h[i] * s_w2[f * 3 + 1];
        p2 += h[i] * s_w2[f * 3 + 2];
    }
#pragma unroll
    for (int off = 4; off; off >>= 1) {
        p0 += __shfl_xor_sync(~0u, p0, off);
        p1 += __shfl_xor_sync(~0u, p1, off);
        p2 += __shfl_xor_sync(~0u, p2, off);
    }
    if (sub == 0) {
        float l0 = p0 + s_b2[0], l1 = p1 + s_b2[1], l2 = p2 + s_b2[2];
        float mx = fmaxf(l0, fmaxf(l1, l2));
        float lse = __logf(__expf(l0 - mx) + __expf(l1 - mx) + __expf(l2 - mx)) + mx;
        outp[(size_t)id * 3 + 0] = l0 - lse;
        outp[(size_t)id * 3 + 1] = l1 - lse;
        outp[(size_t)id * 3 + 2] = l2 - lse;
    }
}

// ---------------- host orchestration -------------------------------------------
extern "C" void kernel_launch(void* const* d_in, const int* in_sizes, int n_in,
                              void* d_out, int out_size) {
    const float* x     = (const float*)d_in[0];
    const void*  eidx  = d_in[1];
    const void*  etyp  = d_in[2];
    const float* W1    = (const float*)d_in[3];
    const float* root1 = (const float*)d_in[4];
    const float* b1    = (const float*)d_in[5];
    const float* W2    = (const float*)d_in[6];
    const float* root2 = (const float*)d_in[7];
    const float* b2    = (const float*)d_in[8];
    const float* W3    = (const float*)d_in[9];
    const float* root3 = (const float*)d_in[10];
    const float* b3    = (const float*)d_in[11];
    const float* ln_g  = (const float*)d_in[12];
    const float* ln_b  = (const float*)d_in[13];
    const float* ew1   = (const float*)d_in[14];
    const float* eb1   = (const float*)d_in[15];
    const float* ew2   = (const float*)d_in[16];
    const float* eb2   = (const float*)d_in[17];
    const float* nw1   = (const float*)d_in[18];
    const float* nb1   = (const float*)d_in[19];
    const float* nw2   = (const float*)d_in[20];
    const float* nb2   = (const float*)d_in[21];
    float* out = (float*)d_out;

    float *p_bufa, *p_bufb;
    uint32_t *p_xr, *p_hb, *p_ea, *p_eb, *p_wt1, *p_wt2, *p_wt3, *p_wte;
    cudaGetSymbolAddress((void**)&p_xr,   g_xr);
    cudaGetSymbolAddress((void**)&p_bufa, g_bufa);
    cudaGetSymbolAddress((void**)&p_bufb, g_bufb);
    cudaGetSymbolAddress((void**)&p_hb,   g_hb);
    cudaGetSymbolAddress((void**)&p_ea,   g_ea);
    cudaGetSymbolAddress((void**)&p_eb,   g_eb);
    cudaGetSymbolAddress((void**)&p_wt1,  g_wt1);
    cudaGetSymbolAddress((void**)&p_wt2,  g_wt2);
    cudaGetSymbolAddress((void**)&p_wt3,  g_wt3);
    cudaGetSymbolAddress((void**)&p_wte,  g_wte);

    const int SMEM_F4 = 61440 + 3 * 4 * 6144;   // 135168 B (fp32-A, NT=4)
    const int SMEM_B4 = 30720 + 3 * 4 * 6144;   // 104448 B (bf16-A, NT=4)
    const int SMEM_B2 = 30720 + 3 * 2 * 6144;   //  67584 B (bf16-A, NT=2)
    cudaFuncSetAttribute((const void*)k_mma<4, 0>, cudaFuncAttributeMaxDynamicSharedMemorySize, SMEM_F4);
    cudaFuncSetAttribute((const void*)k_mma<4, 1>, cudaFuncAttributeMaxDynamicSharedMemorySize, SMEM_B4);
    cudaFuncSetAttribute((const void*)k_mma<2, 1>, cudaFuncAttributeMaxDynamicSharedMemorySize, SMEM_B2);

    int tiles = (NN + 127) / 128;            // 391
    int warpNBlocks = (NN * 32 + 255) / 256;
    int packN = 256 * 400 + 8192 + 8192 + 4096;
    int initB = SCANB + (packN + 255) / 256;
    size_t NH32 = (size_t)NN * 32;

    // 1: init (zero counters + detect + pack weights)
    k_init<<<initB, 256>>>((const unsigned int*)eidx, W1, root1, W2, root2, W3, root3, ew1);

    // 2: layer-1 GEMM + fused edge convert/count backfill
    k_mma<4, 0><<<tiles + CONVB, 512, SMEM_F4>>>(x, p_wt1, NN, FIN, 400,
                                                 p_xr, p_xr + NH32, p_xr + 2 * NH32, p_bufa, b1,
                                                 eidx, etyp, tiles);

    // 3-4: CSR offsets + scatter
    k_off<<<SCANB, 256>>>();
    k_scatter<<<(EE + 255) / 256, 256>>>();

    // 5: layer-1 aggregate + relu -> bf16 h1
    k_agg<<<warpNBlocks, 256>>>(p_xr, p_bufa, p_hb);

    // 6-7: layer 2 (A = bf16 h1)
    k_mma<4, 1><<<tiles, 512, SMEM_B4>>>(p_hb, p_wt2, NN, 64, 32,
                                         p_xr, p_xr + NH32, p_xr + 2 * NH32, p_bufb, b2,
                                         nullptr, nullptr, tiles);
    k_agg<<<warpNBlocks, 256>>>(p_xr, p_bufb, p_hb);

    // 8-9: layer 3 + fused agg/LN/node-head (x3 bf16 -> g_hb)
    k_mma<4, 1><<<tiles, 512, SMEM_B4>>>(p_hb, p_wt3, NN, 64, 32,
                                         p_xr, p_xr + NH32, p_xr + 2 * NH32, p_bufa, b3,
                                         nullptr, nullptr, tiles);
    k_agg_ln_node<<<warpNBlocks, 256>>>(p_xr, p_bufa, p_hb, ln_g, ln_b,
                                        nw1, nb1, nw2, nb2, out);

    // 10-11: edge head (A = x3 bf16)
    k_mma<2, 1><<<tiles, 512, SMEM_B2>>>(p_hb, p_wte, NN, 64, 32,
                                         p_ea, p_eb, nullptr, nullptr, nullptr,
                                         nullptr, nullptr, tiles);
    k_edge<<<(EE * 8 + 255) / 256, 256>>>((const uint4*)p_ea, (const uint4*)p_eb,
                                          eb1, ew2, eb2, out);
}

// round 16
// speedup vs baseline: 1.2085x; 1.0206x over previous
#include <cuda_runtime.h>
#include <math.h>
#include <stdint.h>

#define NN 50000
#define EE 1600000
#define FIN 770
#define RR 3
#define SEG (RR * NN)               // 150000
#define SCANB ((SEG + 255) / 256)   // 586
#define CONVB 1024

// ---------------- scratch ------------------------------------------------------
__device__ uint32_t g_xr[(size_t)RR * NN * 32];   // bf16x2 rows (64 feat = 32 u32)
__device__ float    g_bufa[(size_t)NN * 64];      // fp32 root results
__device__ float    g_bufb[(size_t)NN * 64];
__device__ uint32_t g_hb[(size_t)NN * 32];        // bf16x2 activations (h1/h2/x3)
__device__ uint32_t g_ea[(size_t)NN * 32];
__device__ uint32_t g_eb[(size_t)NN * 32];
__device__ float g_invc[SEG];
__device__ int   g_cnt[SEG];
__device__ int   g_off[SEG];        // after k_off: seg start; after k_scatter: seg end
__device__ int   g_gctr;
__device__ uint32_t g_sd[EE];       // src | dst<<16 (edge order)
__device__ uint8_t  g_et8[EE];
__device__ uint2    g_csr[EE];      // {sd, eid}, CSR order
__device__ int   g_is64;
__device__ uint32_t g_wt1[256 * 400];   // bf16x2 pairs, [N][Kp2]
__device__ uint32_t g_wt2[256 * 32];
__device__ uint32_t g_wt3[256 * 32];
__device__ uint32_t g_wte[128 * 32];

// ---------------- helpers ------------------------------------------------------
__device__ __forceinline__ uint32_t smem_u32(const void* p) {
    uint32_t a;
    asm("{ .reg .u64 t; cvta.to.shared.u64 t, %1; cvt.u32.u64 %0, t; }" : "=r"(a) : "l"(p));
    return a;
}
__device__ __forceinline__ void cp16(uint32_t dst, const void* src, int sz) {
    asm volatile("cp.async.cg.shared.global [%0], [%1], 16, %2;"
                 :: "r"(dst), "l"(src), "r"(sz) : "memory");
}
__device__ __forceinline__ void cp8(uint32_t dst, const void* src, int sz) {
    asm volatile("cp.async.ca.shared.global [%0], [%1], 8, %2;"
                 :: "r"(dst), "l"(src), "r"(sz) : "memory");
}
__device__ __forceinline__ uint32_t f2bf2(float lo, float hi) {
    uint32_t r;
    asm("cvt.rn.bf16x2.f32 %0, %1, %2;" : "=r"(r) : "f"(hi), "f"(lo));
    return r;
}
__device__ __forceinline__ float bflo(uint32_t v) { return __uint_as_float(v << 16); }
__device__ __forceinline__ float bfhi(uint32_t v) { return __uint_as_float(v & 0xFFFF0000u); }
__device__ __forceinline__ void mma16(float* c, const uint32_t* a, uint32_t b0, uint32_t b1) {
    asm volatile(
        "mma.sync.aligned.m16n8k16.row.col.f32.bf16.bf16.f32 "
        "{%0,%1,%2,%3}, {%4,%5,%6,%7}, {%8,%9}, {%0,%1,%2,%3};"
        : "+f"(c[0]), "+f"(c[1]), "+f"(c[2]), "+f"(c[3])
        : "r"(a[0]), "r"(a[1]), "r"(a[2]), "r"(a[3]), "r"(b0), "r"(b1));
}

// ---------------- launch 1: fused detect+zero + weight pack ---------------------
__global__ void k_init(const unsigned int* __restrict__ ei,
                       const float* __restrict__ W1, const float* __restrict__ root1,
                       const float* __restrict__ W2, const float* __restrict__ root2,
                       const float* __restrict__ W3, const float* __restrict__ root3,
                       const float* __restrict__ ew1) {
    int b = blockIdx.x;
    if (b < SCANB) {
        int i = b * 256 + threadIdx.x;
        if (i < SEG) g_cnt[i] = 0;
        if (i == 0) {
            g_gctr = 0;
            int is64 = 1;
            for (int j = 0; j < 64; j++)
                if (ei[2 * j + 1] != 0u) { is64 = 0; break; }
            g_is64 = is64;
        }
        return;
    }
    int i = (b - SCANB) * 256 + threadIdx.x;
    if (i < 256 * 400) {                                 // wt1  [256][400]
        int n = i / 400, s = i % 400;
        int jj = s & 7, k0 = (s >> 3) * 16 + (jj >> 1) * 2 + (jj & 1) * 8;
        float lo = 0.f, hi = 0.f;
        if (n < 192) {
            if (k0 < FIN)     lo = W1[(size_t)(n >> 6) * FIN * 64 + (size_t)k0 * 64 + (n & 63)];
            if (k0 + 1 < FIN) hi = W1[(size_t)(n >> 6) * FIN * 64 + (size_t)(k0 + 1) * 64 + (n & 63)];
        } else {
            if (k0 < FIN)     lo = root1[(size_t)k0 * 64 + (n - 192)];
            if (k0 + 1 < FIN) hi = root1[(size_t)(k0 + 1) * 64 + (n - 192)];
        }
        g_wt1[i] = f2bf2(lo, hi);
        return;
    }
    int j = i - 256 * 400;
    if (j < 8192) {                                      // wt2 [256][32]
        int n = j >> 5, s = j & 31;
        int jj = s & 7, k0 = (s >> 3) * 16 + (jj >> 1) * 2 + (jj & 1) * 8;
        float lo, hi;
        if (n < 192) {
            lo = W2[(n >> 6) * 4096 + k0 * 64 + (n & 63)];
            hi = W2[(n >> 6) * 4096 + (k0 + 1) * 64 + (n & 63)];
        } else {
            lo = root2[k0 * 64 + (n - 192)];
            hi = root2[(k0 + 1) * 64 + (n - 192)];
        }
        g_wt2[j] = f2bf2(lo, hi);
        return;
    }
    j -= 8192;
    if (j < 8192) {                                      // wt3
        int n = j >> 5, s = j & 31;
        int jj = s & 7, k0 = (s >> 3) * 16 + (jj >> 1) * 2 + (jj & 1) * 8;
        float lo, hi;
        if (n < 192) {
            lo = W3[(n >> 6) * 4096 + k0 * 64 + (n & 63)];
            hi = W3[(n >> 6) * 4096 + (k0 + 1) * 64 + (n & 63)];
        } else {
            lo = root3[k0 * 64 + (n - 192)];
            hi = root3[(k0 + 1) * 64 + (n - 192)];
        }
        g_wt3[j] = f2bf2(lo, hi);
        return;
    }
    j -= 8192;
    if (j < 4096) {                                      // wte [128][32]
        int n = j >> 5, s = j & 31;
        int jj = s & 7, k0 = (s >> 3) * 16 + (jj >> 1) * 2 + (jj & 1) * 8;
        float lo, hi;
        if (n < 64) { lo = ew1[k0 * 64 + n];               hi = ew1[(k0 + 1) * 64 + n]; }
        else        { lo = ew1[(64 + k0) * 64 + (n - 64)]; hi = ew1[(64 + k0 + 1) * 64 + (n - 64)]; }
        g_wte[j] = f2bf2(lo, hi);
    }
}

// ---------------- offsets via block scan + global atomic base -------------------
__global__ void k_off() {
    __shared__ int sh[256];
    __shared__ int s_base;
    int tid = threadIdx.x;
    int i = blockIdx.x * 256 + tid;
    int v = (i < SEG) ? g_cnt[i] : 0;
    sh[tid] = v;
    __syncthreads();
    for (int o = 1; o < 256; o <<= 1) {
        int t = (tid >= o) ? sh[tid - o] : 0;
        __syncthreads();
        sh[tid] += t;
        __syncthreads();
    }
    if (tid == 255) s_base = atomicAdd(&g_gctr, sh[255]);
    __syncthreads();
    if (i < SEG) {
        g_off[i] = sh[tid] - v + s_base;
        g_invc[i] = 1.0f / (float)(v > 0 ? v : 1);
    }
}
// scatter: atomic on g_off itself (returns position); packed uint2 store
__global__ void k_scatter() {
    int e = blockIdx.x * blockDim.x + threadIdx.x;
    if (e >= EE) return;
    uint32_t sd = g_sd[e];
    int idx = (int)g_et8[e] * NN + (int)(sd >> 16);
    int pos = atomicAdd(&g_off[idx], 1);
    g_csr[pos] = make_uint2(sd, (uint32_t)e);
}

// ---------------- GEMM: A (fp32 or bf16x2) @ bf16[N,Kp2]^T, N = NT*64 -----------
// 512 threads / 16 warps; MT = NT/2 row-tiles of 16 per warp; 3-stage cp.async.
// Blocks >= mtiles run edge convert+count (fused backfill; ei != nullptr).
template<int NT, int ABF>
__device__ __forceinline__ void issue_chunk(const void* __restrict__ X,
                                            const uint32_t* __restrict__ Wt,
                                            int M, int K, int Kp2, int m0, int c, int buf,
                                            uint32_t sb) {
    int tid = threadIdx.x;
    uint32_t bb = sb + (ABF ? 30720u : 61440u) + (uint32_t)buf * (uint32_t)(NT * 6144);
    if (ABF) {
        uint32_t ab = sb + (uint32_t)buf * 10240u;
        int row = tid >> 2, j = tid & 3;          // 512 units: 128 rows x 4 of 16B
        int ok = (m0 + row) < M;
        const uint32_t* src = (const uint32_t*)X + (size_t)(m0 + row) * Kp2 + c * 16 + j * 4;
        cp16(ab + row * 80 + j * 16, ok ? (const void*)src : X, ok ? 16 : 0);
    } else {
        uint32_t ab = sb + (uint32_t)buf * 20480u;
        int k0 = c * 32;
#pragma unroll
        for (int i = 0; i < 4; i++) {
            int u = i * 512 + tid;                // 2048 units: 128 rows x 16 of 8B
            int row = u >> 4, j = u & 15;
            int kk = k0 + j * 2;
            int ok = ((m0 + row) < M) && (kk < K);
            const float* src = ok ? ((const float*)X + (size_t)(m0 + row) * K + kk)
                                  : (const float*)X;
            int sz = ok ? ((K - kk >= 2) ? 8 : 4) : 0;
            cp8(ab + row * 160 + j * 8, src, sz);
        }
    }
#pragma unroll
    for (int i = 0; i < NT / 2; i++) {
        int u = i * 512 + tid;                    // NT*64 rows x 4 units of 16B
        int r2 = u >> 2, j2 = u & 3;
        cp16(bb + r2 * 96 + j2 * 16, Wt + (size_t)r2 * Kp2 + c * 16 + j2 * 4, 16);
    }
    asm volatile("cp.async.commit_group;" ::: "memory");
}

template<int NT, int ABF>
__global__ __launch_bounds__(512, 1) void k_mma(
    const void* __restrict__ X, const uint32_t* __restrict__ Wt,
    int M, int K, int Kp2,
    uint32_t* __restrict__ ob0, uint32_t* __restrict__ ob1,
    uint32_t* __restrict__ ob2, float* __restrict__ o3fp,
    const float* __restrict__ bias3,
    const void* __restrict__ ei, const void* __restrict__ et, int mtiles)
{
    if (blockIdx.x >= mtiles) {                   // fused edge convert + count
        int base = (blockIdx.x - mtiles) * 512 + threadIdx.x;
        int stride = (gridDim.x - mtiles) * 512;
        if (g_is64) {
            const long long* p = (const long long*)ei;
            const long long* q = (const long long*)et;
            for (int i = base; i < EE; i += stride) {
                int r = (int)p[i], c = (int)p[EE + i], t = (int)q[i];
                g_sd[i] = (uint32_t)r | ((uint32_t)c << 16);
                g_et8[i] = (uint8_t)t;
                atomicAdd(&g_cnt[t * NN + c], 1);
            }
        } else {
            const int* p = (const int*)ei;
            const int* q = (const int*)et;
            for (int i = base; i < EE; i += stride) {
                int r = p[i], c = p[EE + i], t = q[i];
                g_sd[i] = (uint32_t)r | ((uint32_t)c << 16);
                g_et8[i] = (uint8_t)t;
                atomicAdd(&g_cnt[t * NN + c], 1);
            }
        }
        return;
    }

    extern __shared__ float smf[];
    const uint32_t* smu = (const uint32_t*)smf;
    uint32_t sb = smem_u32(smf);
    const int MT = NT / 2;
    int tid = threadIdx.x, wid = tid >> 5, lane = tid & 31;
    int g = lane >> 2, tig = lane & 3;
    int wn = wid % NT, wm = wid / NT;
    int rowbase = wm * MT * 16;
    int m0 = blockIdx.x * 128;
    int NC = (K + 31) / 32;

    float acc[MT][8][4];
#pragma unroll
    for (int mt = 0; mt < MT; mt++)
#pragma unroll
        for (int nt = 0; nt < 8; nt++)
#pragma unroll
            for (int q = 0; q < 4; q++) acc[mt][nt][q] = 0.f;

    issue_chunk<NT, ABF>(X, Wt, M, K, Kp2, m0, 0, 0, sb);
    if (NC > 1) issue_chunk<NT, ABF>(X, Wt, M, K, Kp2, m0, 1, 1, sb);

    int buf = 0;
    for (int c = 0; c < NC; c++) {
        if (c + 2 < NC) {
            int b2 = buf + 2; if (b2 >= 3) b2 -= 3;
            issue_chunk<NT, ABF>(X, Wt, M, K, Kp2, m0, c + 2, b2, sb);
            asm volatile("cp.async.wait_group 2;" ::: "memory");
        } else if (c + 1 < NC) {
            asm volatile("cp.async.wait_group 1;" ::: "memory");
        } else {
            asm volatile("cp.async.wait_group 0;" ::: "memory");
        }
        __syncthreads();

        int bf = (ABF ? 7680 : 15360) + buf * (NT * 1536);   // u32 index
#pragma unroll
        for (int st = 0; st < 2; st++) {
            uint32_t A[MT][4];
#pragma unroll
            for (int mt = 0; mt < MT; mt++) {
                if (ABF) {
                    uint32_t addr = sb + (uint32_t)buf * 10240u
                        + (uint32_t)((rowbase + mt * 16 + (lane & 15)) * 80
                                     + (lane >> 4) * 16 + st * 32);
                    asm volatile(
                        "ldmatrix.sync.aligned.m8n8.x4.shared.b16 {%0,%1,%2,%3}, [%4];"
                        : "=r"(A[mt][0]), "=r"(A[mt][1]), "=r"(A[mt][2]), "=r"(A[mt][3])
                        : "r"(addr));
                } else {
                    int af = buf * 5120;                     // u32 per stage
                    int base = af + (rowbase + mt * 16 + g) * 40 + st * 16 + 2 * tig;
                    float2 x0 = *(const float2*)&smf[base];
                    float2 x1 = *(const float2*)&smf[base + 8 * 40];
                    float2 x2 = *(const float2*)&smf[base + 8];
                    float2 x3 = *(const float2*)&smf[base + 8 * 40 + 8];
                    A[mt][0] = f2bf2(x0.x, x0.y);
                    A[mt][1] = f2bf2(x1.x, x1.y);
                    A[mt][2] = f2bf2(x2.x, x2.y);
                    A[mt][3] = f2bf2(x3.x, x3.y);
                }
            }
#pragma unroll
            for (int nt = 0; nt < 8; nt++) {
                int nb = bf + (wn * 64 + nt * 8 + g) * 24 + st * 8 + tig * 2;
                uint2 bv = *(const uint2*)&smu[nb];
#pragma unroll
                for (int mt = 0; mt < MT; mt++)
                    mma16(acc[mt][nt], A[mt], bv.x, bv.y);
            }
        }
        __syncthreads();
        buf = (buf + 1 == 3) ? 0 : buf + 1;
    }

    bool fp = (wn == NT - 1) && (o3fp != nullptr);
    uint32_t* ob = (wn == 0) ? ob0 : ((wn == 1) ? ob1 : ob2);
#pragma unroll
    for (int mt = 0; mt < MT; mt++) {
        int mA = m0 + rowbase + mt * 16 + g;
        int mB = mA + 8;
#pragma unroll
        for (int nt = 0; nt < 8; nt++) {
            int col = nt * 8 + tig * 2;
            float c0 = acc[mt][nt][0], c1 = acc[mt][nt][1];
            float c2 = acc[mt][nt][2], c3 = acc[mt][nt][3];
            if (fp) {
                float bb0 = bias3[col], bb1 = bias3[col + 1];
                c0 += bb0; c1 += bb1; c2 += bb0; c3 += bb1;
                if (mA < M) *(float2*)(o3fp + (size_t)mA * 64 + col) = make_float2(c0, c1);
                if (mB < M) *(float2*)(o3fp + (size_t)mB * 64 + col) = make_float2(c2, c3);
            } else {
                if (mA < M) ob[(size_t)mA * 32 + (col >> 1)] = f2bf2(c0, c1);
                if (mB < M) ob[(size_t)mB * 32 + (col >> 1)] = f2bf2(c2, c3);
            }
        }
    }
}

// ---------------- CSR aggregation core: bf16 gathers (feat 2l, 2l+1) ------------
// NOTE: g_off[idx] is the segment END after k_scatter; beg = end - n.
__device__ __forceinline__ void agg_core(const uint32_t* __restrict__ xr, int w, int lane,
                                         float& a0, float& a1) {
#pragma unroll
    for (int r = 0; r < RR; r++) {
        int idx = r * NN + w;
        int n = g_cnt[idx];
        int beg = g_off[idx] - n;
        const uint32_t* xrr = xr + (size_t)r * NN * 32;
        float s0 = 0.f, s1 = 0.f;
        for (int b = 0; b < n; b += 32) {
            int src = (b + lane < n) ? (int)(g_csr[beg + b + lane].x & 0xFFFFu) : 0;
            int m = min(32, n - b);
            int j = 0;
            for (; j + 8 <= m; j += 8) {
                uint32_t v[8];
#pragma unroll
                for (int q = 0; q < 8; q++)
                    v[q] = xrr[(size_t)__shfl_sync(~0u, src, j + q) * 32 + lane];
                float t0 = 0.f, t1 = 0.f;
#pragma unroll
                for (int q = 0; q < 8; q++) {
                    t0 += bflo(v[q]);
                    t1 += bfhi(v[q]);
                }
                s0 += t0; s1 += t1;
            }
            for (; j + 4 <= m; j += 4) {
                uint32_t v[4];
#pragma unroll
                for (int q = 0; q < 4; q++)
                    v[q] = xrr[(size_t)__shfl_sync(~0u, src, j + q) * 32 + lane];
#pragma unroll
                for (int q = 0; q < 4; q++) {
                    s0 += bflo(v[q]);
                    s1 += bfhi(v[q]);
                }
            }
            for (; j < m; j++) {
                uint32_t v = xrr[(size_t)__shfl_sync(~0u, src, j) * 32 + lane];
                s0 += bflo(v);
                s1 += bfhi(v);
            }
        }
        float ic = g_invc[idx];
        a0 += s0 * ic;
        a1 += s1 * ic;
    }
}

// agg + relu -> bf16x2 activation buffer
__global__ void k_agg(const uint32_t* __restrict__ xr, const float* __restrict__ io,
                      uint32_t* __restrict__ outb) {
    int w = (blockIdx.x * blockDim.x + threadIdx.x) >> 5;
    int lane = threadIdx.x & 31;
    if (w >= NN) return;
    float a0 = 0.f, a1 = 0.f;
    agg_core(xr, w, lane, a0, a1);
    float2 cur = *(const float2*)&io[(size_t)w * 64 + 2 * lane];
    float v0 = fmaxf(cur.x + a0, 0.f);
    float v1 = fmaxf(cur.y + a1, 0.f);
    outb[(size_t)w * 32 + lane] = f2bf2(v0, v1);
}

// ---------------- fused: agg(layer3) + LayerNorm + node head --------------------
__global__ void k_agg_ln_node(const uint32_t* __restrict__ xr, const float* __restrict__ io,
                              uint32_t* __restrict__ x3out,
                              const float* __restrict__ gg, const float* __restrict__ bb,
                              const float* __restrict__ nw1, const float* __restrict__ nb1,
                              const float* __restrict__ nw2, const float* __restrict__ nb2,
                              float* __restrict__ outp) {
    __shared__ float s_w1[64 * 32];
    __shared__ float s_b1[32], s_w2[64], s_b2[2], s_g[64], s_bb[64];
    int tid = threadIdx.x;
    for (int i = tid; i < 2048; i += blockDim.x) s_w1[i] = nw1[i];
    if (tid < 32) s_b1[tid] = nb1[tid];
    if (tid < 64) { s_w2[tid] = nw2[tid]; s_g[tid] = gg[tid]; s_bb[tid] = bb[tid]; }
    if (tid < 2)  s_b2[tid] = nb2[tid];
    __syncthreads();

    int w = (blockIdx.x * blockDim.x + tid) >> 5;
    int lane = tid & 31;
    if (w >= NN) return;
    float a0 = 0.f, a1 = 0.f;
    agg_core(xr, w, lane, a0, a1);
    float2 cur = *(const float2*)&io[(size_t)w * 64 + 2 * lane];
    float v0 = cur.x + a0;
    float v1 = cur.y + a1;

    float s = v0 + v1;
#pragma unroll
    for (int off = 16; off; off >>= 1) s += __shfl_xor_sync(~0u, s, off);
    float mu = s * (1.f / 64.f);
    float d0 = v0 - mu, d1 = v1 - mu;
    float q = d0 * d0 + d1 * d1;
#pragma unroll
    for (int off = 16; off; off >>= 1) q += __shfl_xor_sync(~0u, q, off);
    float rs = rsqrtf(q * (1.f / 64.f) + 1e-5f);
    float xa = d0 * rs * s_g[2 * lane]     + s_bb[2 * lane];
    float xb = d1 * rs * s_g[2 * lane + 1] + s_bb[2 * lane + 1];
    x3out[(size_t)w * 32 + lane] = f2bf2(xa, xb);

    float acc = s_b1[lane];
#pragma unroll
    for (int k = 0; k < 32; k++) {
        float x0 = __shfl_sync(~0u, xa, k);
        float x1 = __shfl_sync(~0u, xb, k);
        acc += x0 * s_w1[(2 * k) * 32 + lane] + x1 * s_w1[(2 * k + 1) * 32 + lane];
    }
    float nh = fmaxf(acc, 0.f);
    float p0 = nh * s_w2[lane * 2 + 0];
    float p1 = nh * s_w2[lane * 2 + 1];
#pragma unroll
    for (int off = 16; off; off >>= 1) {
        p0 += __shfl_xor_sync(~0u, p0, off);
        p1 += __shfl_xor_sync(~0u, p1, off);
    }
    if (lane == 0) {
        float l0 = p0 + s_b2[0], l1 = p1 + s_b2[1];
        float mx = fmaxf(l0, l1);
        float lse = __logf(__expf(l0 - mx) + __expf(l1 - mx)) + mx;
        outp[(size_t)3 * EE + (size_t)w * 2 + 0] = l0 - lse;
        outp[(size_t)3 * EE + (size_t)w * 2 + 1] = l1 - lse;
    }
}

// ---------------- edge classifier, CSR order, 8 lanes/edge, uint4 gathers -------
__global__ void k_edge(const uint4* __restrict__ ea4, const uint4* __restrict__ eb4,
                       const float* __restrict__ eb1, const float* __restrict__ ew2,
                       const float* __restrict__ eb2, float* __restrict__ outp) {
    __shared__ float s_b1[64], s_w2[192], s_b2[3];
    int tid = threadIdx.x;
    if (tid < 64)  s_b1[tid] = eb1[tid];
    if (tid < 192) s_w2[tid] = ew2[tid];
    if (tid < 3)   s_b2[tid] = eb2[tid];
    __syncthreads();

    int gid = blockIdx.x * blockDim.x + tid;
    int p = gid >> 3, sub = tid & 7;
    if (p >= EE) return;
    uint2 ce = g_csr[p];
    int r  = (int)(ce.x & 0xFFFFu);
    int c  = (int)(ce.x >> 16);
    int id = (int)ce.y;
    uint4 va = ea4[(size_t)r * 8 + sub];     // feats 8sub..8sub+7
    uint4 vb = eb4[(size_t)c * 8 + sub];
    float h[8];
    h[0] = fmaxf(bflo(va.x) + bflo(vb.x) + s_b1[sub * 8 + 0], 0.f);
    h[1] = fmaxf(bfhi(va.x) + bfhi(vb.x) + s_b1[sub * 8 + 1], 0.f);
    h[2] = fmaxf(bflo(va.y) + bflo(vb.y) + s_b1[sub * 8 + 2], 0.f);
    h[3] = fmaxf(bfhi(va.y) + bfhi(vb.y) + s_b1[sub * 8 + 3], 0.f);
    h[4] = fmaxf(bflo(va.z) + bflo(vb.z) + s_b1[sub * 8 + 4], 0.f);
    h[5] = fmaxf(bfhi(va.z) + bfhi(vb.z) + s_b1[sub * 8 + 5], 0.f);
    h[6] = fmaxf(bflo(va.w) + bflo(vb.w) + s_b1[sub * 8 + 6], 0.f);
    h[7] = fmaxf(bfhi(va.w) + bfhi(vb.w) + s_b1[sub * 8 + 7], 0.f);
    float p0 = 0.f, p1 = 0.f, p2 = 0.f;
#pragma unroll
    for (int i = 0; i < 8; i++) {
        int f = sub * 8 + i;
        p0 += h[i] * s_w2[f * 3 + 0];
        p1 += h[i] * s_w2[f * 3 + 1];
        p2 += h[i] * s_w2[f * 3 + 2];
    }
#pragma unroll
    for (int off = 4; off; off >>= 1) {
        p0 += __shfl_xor_sync(~0u, p0, off);
        p1 += __shfl_xor_sync(~0u, p1, off);
        p2 += __shfl_xor_sync(~0u, p2, off);
    }
    if (sub == 0) {
        float l0 = p0 + s_b2[0], l1 = p1 + s_b2[1], l2 = p2 + s_b2[2];
        float mx = fmaxf(l0, fmaxf(l1, l2));
        float lse = __logf(__expf(l0 - mx) + __expf(l1 - mx) + __expf(l2 - mx)) + mx;
        outp[(size_t)id * 3 + 0] = l0 - lse;
        outp[(size_t)id * 3 + 1] = l1 - lse;
        outp[(size_t)id * 3 + 2] = l2 - lse;
    }
}

// ---------------- host orchestration -------------------------------------------
extern "C" void kernel_launch(void* const* d_in, const int* in_sizes, int n_in,
                              void* d_out, int out_size) {
    const float* x     = (const float*)d_in[0];
    const void*  eidx  = d_in[1];
    const void*  etyp  = d_in[2];
    const float* W1    = (const float*)d_in[3];
    const float* root1 = (const float*)d_in[4];
    const float* b1    = (const float*)d_in[5];
    const float* W2    = (const float*)d_in[6];
    const float* root2 = (const float*)d_in[7];
    const float* b2    = (const float*)d_in[8];
    const float* W3    = (const float*)d_in[9];
    const float* root3 = (const float*)d_in[10];
    const float* b3    = (const float*)d_in[11];
    const float* ln_g  = (const float*)d_in[12];
    const float* ln_b  = (const float*)d_in[13];
    const float* ew1   = (const float*)d_in[14];
    const float* eb1   = (const float*)d_in[15];
    const float* ew2   = (const float*)d_in[16];
    const float* eb2   = (const float*)d_in[17];
    const float* nw1   = (const float*)d_in[18];
    const float* nb1   = (const float*)d_in[19];
    const float* nw2   = (const float*)d_in[20];
    const float* nb2   = (const float*)d_in[21];
    float* out = (float*)d_out;

    float *p_bufa, *p_bufb;
    uint32_t *p_xr, *p_hb, *p_ea, *p_eb, *p_wt1, *p_wt2, *p_wt3, *p_wte;
    cudaGetSymbolAddress((void**)&p_xr,   g_xr);
    cudaGetSymbolAddress((void**)&p_bufa, g_bufa);
    cudaGetSymbolAddress((void**)&p_bufb, g_bufb);
    cudaGetSymbolAddress((void**)&p_hb,   g_hb);
    cudaGetSymbolAddress((void**)&p_ea,   g_ea);
    cudaGetSymbolAddress((void**)&p_eb,   g_eb);
    cudaGetSymbolAddress((void**)&p_wt1,  g_wt1);
    cudaGetSymbolAddress((void**)&p_wt2,  g_wt2);
    cudaGetSymbolAddress((void**)&p_wt3,  g_wt3);
    cudaGetSymbolAddress((void**)&p_wte,  g_wte);

    const int SMEM_F4 = 61440 + 3 * 4 * 6144;   // 135168 B (fp32-A, NT=4)
    const int SMEM_B4 = 30720 + 3 * 4 * 6144;   // 104448 B (bf16-A, NT=4)
    const int SMEM_B2 = 30720 + 3 * 2 * 6144;   //  67584 B (bf16-A, NT=2)
    cudaFuncSetAttribute((const void*)k_mma<4, 0>, cudaFuncAttributeMaxDynamicSharedMemorySize, SMEM_F4);
    cudaFuncSetAttribute((const void*)k_mma<4, 1>, cudaFuncAttributeMaxDynamicSharedMemorySize, SMEM_B4);
    cudaFuncSetAttribute((const void*)k_mma<2, 1>, cudaFuncAttributeMaxDynamicSharedMemorySize, SMEM_B2);

    int tiles = (NN + 127) / 128;            // 391
    int warpNBlocks = (NN * 32 + 255) / 256;
    int packN = 256 * 400 + 8192 + 8192 + 4096;
    int initB = SCANB + (packN + 255) / 256;
    size_t NH32 = (size_t)NN * 32;

    // 1: init (zero counters + detect + pack weights)
    k_init<<<initB, 256>>>((const unsigned int*)eidx, W1, root1, W2, root2, W3, root3, ew1);

    // 2: layer-1 GEMM + fused edge convert/count backfill
    k_mma<4, 0><<<tiles + CONVB, 512, SMEM_F4>>>(x, p_wt1, NN, FIN, 400,
                                                 p_xr, p_xr + NH32, p_xr + 2 * NH32, p_bufa, b1,
                                                 eidx, etyp, tiles);

    // 3-4: CSR offsets + scatter (profiled slot 4 = scatter)
    k_off<<<SCANB, 256>>>();
    k_scatter<<<(EE + 255) / 256, 256>>>();

    // 5: layer-1 aggregate + relu -> bf16 h1
    k_agg<<<warpNBlocks, 256>>>(p_xr, p_bufa, p_hb);

    // 6-7: layer 2 (A = bf16 h1)
    k_mma<4, 1><<<tiles, 512, SMEM_B4>>>(p_hb, p_wt2, NN, 64, 32,
                                         p_xr, p_xr + NH32, p_xr + 2 * NH32, p_bufb, b2,
                                         nullptr, nullptr, tiles);
    k_agg<<<warpNBlocks, 256>>>(p_xr, p_bufb, p_hb);

    // 8-9: layer 3 + fused agg/LN/node-head (x3 bf16 -> g_hb)
    k_mma<4, 1><<<tiles, 512, SMEM_B4>>>(p_hb, p_wt3, NN, 64, 32,
                                         p_xr, p_xr + NH32, p_xr + 2 * NH32, p_bufa, b3,
                                         nullptr, nullptr, tiles);
    k_agg_ln_node<<<warpNBlocks, 256>>>(p_xr, p_bufa, p_hb, ln_g, ln_b,
                                        nw1, nb1, nw2, nb2, out);

    // 10-11: edge head (A = x3 bf16)
    k_mma<2, 1><<<tiles, 512, SMEM_B2>>>(p_hb, p_wte, NN, 64, 32,
                                         p_ea, p_eb, nullptr, nullptr, nullptr,
                                         nullptr, nullptr, tiles);
    k_edge<<<(EE * 8 + 255) / 256, 256>>>((const uint4*)p_ea, (const uint4*)p_eb,
                                          eb1, ew2, eb2, out);
}